// round 8
// baseline (speedup 1.0000x reference)
#include <cuda_runtime.h>
#include <math.h>
#include <stdint.h>

#define N_TOK    4096
#define DIM      512
#define N_EXP    16
#define TOPK     4
#define HID      2048
#define PAIR_CAP 18432          // 16384 pairs + 16 experts * 128 pad
#define MAX_T128 144

// ---------------- device scratch -------------------------------------------
__device__ int8_t g_xq1[N_TOK * DIM];
__device__ int8_t g_xq2[N_TOK * DIM];
__device__ float  g_xs [N_TOK];
__device__ float  g_h  [N_TOK * DIM];
__device__ int8_t g_hq1[N_TOK * DIM];
__device__ int8_t g_hq2[N_TOK * DIM];
__device__ float  g_hs [N_TOK];
__device__ float  g_r  [N_TOK * DIM];
// weights: transposed [Z][N][K] int8 limbs + per-col scale [Z][N]
__device__ int8_t g_pwq1[2 * DIM * DIM];
__device__ int8_t g_pwq2[2 * DIM * DIM];
__device__ float  g_pwt [2 * DIM];
__device__ int8_t g_rwq1[2 * DIM * DIM];
__device__ int8_t g_rwq2[2 * DIM * DIM];
__device__ float  g_rwt [2 * DIM];
__device__ int8_t g_w1q1[N_EXP * HID * DIM];
__device__ int8_t g_w1q2[N_EXP * HID * DIM];
__device__ float  g_w1t [N_EXP * HID];
__device__ int8_t g_w2q1[N_EXP * DIM * HID];
__device__ int8_t g_w2q2[N_EXP * DIM * HID];
__device__ float  g_w2t [N_EXP * DIM];
// gathered activations / hidden
__device__ int8_t g_agq1[PAIR_CAP * DIM];
__device__ int8_t g_agq2[PAIR_CAP * DIM];
__device__ float  g_ags [PAIR_CAP];
__device__ float  g_hid [(size_t)PAIR_CAP * HID];
__device__ int8_t g_hidq1[(size_t)PAIR_CAP * HID];
__device__ int8_t g_hidq2[(size_t)PAIR_CAP * HID];
__device__ float  g_hids [PAIR_CAP];
__device__ float  g_slot[(size_t)PAIR_CAP * DIM];

__device__ int   g_pair_token[PAIR_CAP];
__device__ float g_pair_gate [PAIR_CAP];
__device__ int   g_pairpos [N_TOK * TOPK];
__device__ int   g_tok_eidx[N_TOK * TOPK];
__device__ float g_tok_gate[N_TOK * TOPK];
__device__ int   g_counts [N_EXP];
__device__ int   g_offsets[N_EXP + 1];
__device__ int   g_cursor [N_EXP];
__device__ int   g_t128_e [MAX_T128];
__device__ int   g_t128_m0[MAX_T128];
__device__ int   g_nt128;

// ---------------- asm helpers ----------------------------------------------
__device__ __forceinline__ uint32_t smem_u32(const void* p) {
    uint32_t a;
    asm("{ .reg .u64 t; cvta.to.shared.u64 t, %1; cvt.u32.u64 %0, t; }" : "=r"(a) : "l"(p));
    return a;
}
__device__ __forceinline__ void cpa16(uint32_t s, const void* g) {
    asm volatile("cp.async.cg.shared.global [%0], [%1], 16;" :: "r"(s), "l"(g));
}
#define CP_COMMIT() asm volatile("cp.async.commit_group;" ::: "memory")
#define CP_WAIT(n)  asm volatile("cp.async.wait_group %0;" :: "n"(n) : "memory")

__device__ __forceinline__ void ldm_x4(uint32_t* r, uint32_t a) {
    asm volatile("ldmatrix.sync.aligned.m8n8.x4.shared.b16 {%0,%1,%2,%3}, [%4];"
        : "=r"(r[0]), "=r"(r[1]), "=r"(r[2]), "=r"(r[3]) : "r"(a));
}
__device__ __forceinline__ void mma_s8(int* d, const uint32_t* a, uint32_t b0, uint32_t b1) {
    asm volatile("mma.sync.aligned.m16n8k32.row.col.s32.s8.s8.s32 "
        "{%0,%1,%2,%3}, {%4,%5,%6,%7}, {%8,%9}, {%0,%1,%2,%3};"
        : "+r"(d[0]), "+r"(d[1]), "+r"(d[2]), "+r"(d[3])
        : "r"(a[0]), "r"(a[1]), "r"(a[2]), "r"(a[3]), "r"(b0), "r"(b1));
}
__device__ __forceinline__ float gelu_exact(float x) {
    return 0.5f * x * (1.0f + erff(x * 0.70710678118654752440f));
}

// ---------------- int8 IMMA GEMM: D[128,128] tile --------------------------
// A [M][K] s8 limbs (row scale s), B^T [Z][N][K] s8 limbs (col scale t).
// C = s_i t_j (A1B1 + (A1B2 + A2B1)/128). 8 warps, 64x32 warp tiles.
// MODE 0: proj (+bias -> g_h fp32)  1: router (-> g_r)
// MODE 2: ffn1 (+bias,gelu -> g_hid)  3: ffn2 (+bias,*gate -> g_slot)
#define STG 24576   // 4 x 128 rows x 48B pitch
#define SMEM_DYN (3 * STG)

template<int MODE, int KLEN, int NTOT>
__global__ __launch_bounds__(256, 1) void imma_gemm_kernel(
    const int8_t* __restrict__ Aq1, const int8_t* __restrict__ Aq2,
    const float* __restrict__ Ascale,
    const int8_t* __restrict__ Bq1, const int8_t* __restrict__ Bq2,
    const float* __restrict__ Bscale,
    const float* __restrict__ bias, int zview)
{
    constexpr int NC = KLEN / 32;
    int n0 = blockIdx.x * 128, m0, z;
    if (MODE <= 1) { m0 = blockIdx.y * 128; z = zview; }
    else {
        if ((int)blockIdx.y >= g_nt128) return;
        z = g_t128_e[blockIdx.y]; m0 = g_t128_m0[blockIdx.y];
    }
    const int8_t* B1z = Bq1 + (size_t)z * NTOT * KLEN;
    const int8_t* B2z = Bq2 + (size_t)z * NTOT * KLEN;

    extern __shared__ __align__(16) char smem[];
    uint32_t sb = smem_u32(smem);

    const int tid = threadIdx.x, lane = tid & 31, warp = tid >> 5;
    const int mw = (warp & 1) * 64, nwp = (warp >> 1) * 32;

    auto load_stage = [&](int s, int c) {
        const int k0 = c * 32;
        const uint32_t base = sb + (uint32_t)s * STG;
        int row = tid >> 1, hf = tid & 1;
        uint32_t off = (uint32_t)(row * 48 + hf * 16);
        const int8_t* ap1 = Aq1 + (size_t)(m0 + row) * KLEN + k0 + hf * 16;
        const int8_t* ap2 = Aq2 + (size_t)(m0 + row) * KLEN + k0 + hf * 16;
        const int8_t* bp1 = B1z + (size_t)(n0 + row) * KLEN + k0 + hf * 16;
        const int8_t* bp2 = B2z + (size_t)(n0 + row) * KLEN + k0 + hf * 16;
        cpa16(base +         off, ap1);
        cpa16(base +  6144 + off, ap2);
        cpa16(base + 12288 + off, bp1);
        cpa16(base + 18432 + off, bp2);
    };

    int P[4][4][4], Q[4][4][4];
#pragma unroll
    for (int a = 0; a < 4; a++)
#pragma unroll
        for (int b = 0; b < 4; b++)
#pragma unroll
            for (int d = 0; d < 4; d++) { P[a][b][d] = 0; Q[a][b][d] = 0; }

    load_stage(0, 0); CP_COMMIT();
    if (NC > 1) { load_stage(1, 1); CP_COMMIT(); }

    // fragment address components
    const uint32_t a_off = (uint32_t)((mw + (lane & 15)) * 48 + (lane >> 4) * 16);
    const uint32_t b_off = (uint32_t)((nwp + ((lane >> 4) << 3) + (lane & 7)) * 48
                                      + ((lane >> 3) & 1) * 16);

    for (int c = 0; c < NC; c++) {
        if (c + 2 < NC) { load_stage((c + 2) % 3, c + 2); CP_COMMIT(); CP_WAIT(2); }
        else if (c + 1 < NC) CP_WAIT(1);
        else CP_WAIT(0);
        __syncthreads();

        const uint32_t base = sb + (uint32_t)(c % 3) * STG;
        uint32_t a1[4][4], a2[4][4], b1[2][4], b2[2][4];
#pragma unroll
        for (int ms = 0; ms < 4; ms++) {
            uint32_t ad = base + a_off + (uint32_t)(ms * 16 * 48);
            ldm_x4(a1[ms], ad);
            ldm_x4(a2[ms], ad + 6144);
        }
#pragma unroll
        for (int g = 0; g < 2; g++) {              // each x4 covers 2 n8-tiles
            uint32_t bd = base + 12288 + b_off + (uint32_t)(g * 16 * 48);
            ldm_x4(b1[g], bd);
            ldm_x4(b2[g], bd + 6144);
        }
#pragma unroll
        for (int ms = 0; ms < 4; ms++)
#pragma unroll
            for (int nt = 0; nt < 4; nt++) {
                uint32_t c10 = b1[nt >> 1][(nt & 1) * 2], c11 = b1[nt >> 1][(nt & 1) * 2 + 1];
                uint32_t c20 = b2[nt >> 1][(nt & 1) * 2], c21 = b2[nt >> 1][(nt & 1) * 2 + 1];
                mma_s8(P[ms][nt], a1[ms], c10, c11);
                mma_s8(Q[ms][nt], a1[ms], c20, c21);
                mma_s8(Q[ms][nt], a2[ms], c10, c11);
            }
        __syncthreads();
    }

    // ---- epilogue ----
    float* OUT = (MODE == 0) ? g_h : (MODE == 1) ? g_r : (MODE == 2) ? g_hid : g_slot;
    const int lrow = lane >> 2, lcol = (lane & 3) * 2;
#pragma unroll
    for (int ms = 0; ms < 4; ms++) {
        int r0 = m0 + mw + ms * 16 + lrow;
        float s0 = Ascale[r0], s1 = Ascale[r0 + 8];
        float gt0 = 0.f, gt1 = 0.f;
        if (MODE == 3) { gt0 = g_pair_gate[r0]; gt1 = g_pair_gate[r0 + 8]; }
#pragma unroll
        for (int nt = 0; nt < 4; nt++) {
            int cc = n0 + nwp + nt * 8 + lcol;
            float t0 = Bscale[(size_t)z * NTOT + cc];
            float t1 = Bscale[(size_t)z * NTOT + cc + 1];
            float b0 = 0.f, b1v = 0.f;
            if (MODE != 1) {
                b0  = bias[(size_t)z * NTOT + cc];
                b1v = bias[(size_t)z * NTOT + cc + 1];
            }
            const float inv128 = 0.0078125f;
            float v00 = s0 * t0 * ((float)P[ms][nt][0] + (float)Q[ms][nt][0] * inv128) + b0;
            float v01 = s0 * t1 * ((float)P[ms][nt][1] + (float)Q[ms][nt][1] * inv128) + b1v;
            float v10 = s1 * t0 * ((float)P[ms][nt][2] + (float)Q[ms][nt][2] * inv128) + b0;
            float v11 = s1 * t1 * ((float)P[ms][nt][3] + (float)Q[ms][nt][3] * inv128) + b1v;
            if (MODE == 2) {
                v00 = gelu_exact(v00); v01 = gelu_exact(v01);
                v10 = gelu_exact(v10); v11 = gelu_exact(v11);
            }
            if (MODE == 3) { v00 *= gt0; v01 *= gt0; v10 *= gt1; v11 *= gt1; }
            *(float2*)(OUT + (size_t)r0 * NTOT + cc)       = make_float2(v00, v01);
            *(float2*)(OUT + (size_t)(r0 + 8) * NTOT + cc) = make_float2(v10, v11);
        }
    }
}

// ---------------- quantization kernels --------------------------------------
// per-row two-limb quant: in [R][C] fp32 -> q1,q2 [R][C] s8, scale [R]
template<int C>
__global__ __launch_bounds__(128) void quant_rows_kernel(
    const float* __restrict__ in, int8_t* __restrict__ q1,
    int8_t* __restrict__ q2, float* __restrict__ scale)
{
    int r = blockIdx.x;
    const float* row = in + (size_t)r * C;
    int tid = threadIdx.x;
    __shared__ float wmax[4];
    float mx = 0.f;
    for (int i = tid * 4; i < C; i += 512) {
        float4 v = *(const float4*)(row + i);
        mx = fmaxf(mx, fmaxf(fmaxf(fabsf(v.x), fabsf(v.y)), fmaxf(fabsf(v.z), fabsf(v.w))));
    }
#pragma unroll
    for (int o = 16; o > 0; o >>= 1)
        mx = fmaxf(mx, __shfl_xor_sync(0xFFFFFFFF, mx, o));
    if ((tid & 31) == 0) wmax[tid >> 5] = mx;
    __syncthreads();
    mx = fmaxf(fmaxf(wmax[0], wmax[1]), fmaxf(wmax[2], wmax[3]));
    float s = fmaxf(mx, 1e-20f) * (1.0f / 127.0f);
    float inv = 1.0f / s;
    if (tid == 0) scale[r] = s;
    for (int i = tid * 4; i < C; i += 512) {
        float4 v = *(const float4*)(row + i);
        float f[4] = {v.x, v.y, v.z, v.w};
        char c1[4], c2[4];
#pragma unroll
        for (int j = 0; j < 4; j++) {
            float q = rintf(f[j] * inv);
            float rres = f[j] * inv - q;
            c1[j] = (char)(int)q;
            c2[j] = (char)(int)rintf(rres * 128.0f);
        }
        *(uint32_t*)(q1 + (size_t)r * C + i) = *(uint32_t*)c1;
        *(uint32_t*)(q2 + (size_t)r * C + i) = *(uint32_t*)c2;
    }
}

// weight col-max: B [Z][K][N] -> t [Z][N]
__global__ __launch_bounds__(256) void colmax_kernel(
    const float* __restrict__ B, float* __restrict__ t, int K, int N)
{
    int n = blockIdx.x * 256 + threadIdx.x;
    int z = blockIdx.y;
    if (n >= N) return;
    const float* Bz = B + (size_t)z * K * N;
    float mx = 0.f;
    for (int k = 0; k < K; k++) mx = fmaxf(mx, fabsf(Bz[(size_t)k * N + n]));
    t[(size_t)z * N + n] = fmaxf(mx, 1e-20f) * (1.0f / 127.0f);
}

// transpose + quant: B [Z][K][N] fp32 -> q1t,q2t [Z][N][K] s8
__global__ __launch_bounds__(256) void tq_kernel(
    const float* __restrict__ B, const float* __restrict__ t,
    int8_t* __restrict__ q1t, int8_t* __restrict__ q2t, int K, int N)
{
    __shared__ float tile[32][33];
    int z = blockIdx.z;
    int n0 = blockIdx.x * 32, k0 = blockIdx.y * 32;
    int tx = threadIdx.x, ty = threadIdx.y;
    const float* Bz = B + (size_t)z * K * N;
#pragma unroll
    for (int i = 0; i < 32; i += 8)
        tile[ty + i][tx] = Bz[(size_t)(k0 + ty + i) * N + n0 + tx];
    __syncthreads();
#pragma unroll
    for (int i = 0; i < 32; i += 8) {
        int n = n0 + ty + i;
        float inv = 1.0f / t[(size_t)z * N + n];
        float v = tile[tx][ty + i];
        float q = rintf(v * inv);
        float rres = v * inv - q;
        size_t oi = (size_t)z * N * K + (size_t)n * K + k0 + tx;
        q1t[oi] = (char)(int)q;
        q2t[oi] = (char)(int)rintf(rres * 128.0f);
    }
}

// ---------------- routing kernels -------------------------------------------
__global__ __launch_bounds__(128) void gate_kernel(const float* __restrict__ keys)
{
    const int t = blockIdx.x;
    __shared__ float rs[DIM];
    __shared__ float part[N_EXP][8];
    __shared__ float logit[N_EXP];
    const int tid = threadIdx.x;
    for (int i = tid; i < DIM; i += 128) rs[i] = g_r[(size_t)t * DIM + i];
    __syncthreads();
    const int e = tid >> 3, l = tid & 7;
    const float* kp = keys + (size_t)e * DIM;
    float s = 0.f;
    for (int i = l; i < DIM; i += 8) { float d = rs[i] - kp[i]; s = fmaf(d, d, s); }
    part[e][l] = s;
    __syncthreads();
    if (l == 0) {
        float d2 = 0.f;
#pragma unroll
        for (int j = 0; j < 8; j++) d2 += part[e][j];
        logit[e] = -sqrtf(fmaxf(d2, 0.f));
    }
    __syncthreads();
    if (tid == 0) {
        float lv[N_EXP];
#pragma unroll
        for (int i = 0; i < N_EXP; i++) lv[i] = logit[i];
        int idx[TOPK]; float val[TOPK]; bool used[N_EXP];
#pragma unroll
        for (int i = 0; i < N_EXP; i++) used[i] = false;
        for (int s2 = 0; s2 < TOPK; s2++) {
            int bi = -1; float bv = -1e30f;
            for (int i = 0; i < N_EXP; i++)
                if (!used[i] && lv[i] > bv) { bv = lv[i]; bi = i; }
            used[bi] = true; idx[s2] = bi; val[s2] = bv;
        }
        float mx = val[0], ex[TOPK], se = 0.f;
        for (int s2 = 0; s2 < TOPK; s2++) { ex[s2] = expf(val[s2] - mx); se += ex[s2]; }
        float inv = 1.0f / se;
        for (int s2 = 0; s2 < TOPK; s2++) {
            g_tok_eidx[t*TOPK + s2] = idx[s2];
            g_tok_gate[t*TOPK + s2] = ex[s2] * inv;
            atomicAdd(&g_counts[idx[s2]], 1);
        }
    }
}

__global__ __launch_bounds__(256) void reset_kernel() {
    int i = blockIdx.x * 256 + threadIdx.x;
    if (i < PAIR_CAP) { g_pair_token[i] = -1; g_pair_gate[i] = 0.f; g_ags[i] = 1.0f; }
    if (i < N_EXP) g_counts[i] = 0;
}

__global__ void scan_kernel() {
    if (threadIdx.x == 0) {
        int o = 0, n128 = 0;
        for (int e = 0; e < N_EXP; e++) {
            g_offsets[e] = o; g_cursor[e] = o;
            int seg = ((g_counts[e] + 127) >> 7) << 7;
            for (int i = 0; i < seg / 128; i++) { g_t128_e[n128] = e; g_t128_m0[n128] = o + i * 128; n128++; }
            o += seg;
        }
        g_offsets[N_EXP] = o;
        g_nt128 = n128;
    }
}

__global__ __launch_bounds__(128) void scatter_kernel() {
    int t = blockIdx.x * 128 + threadIdx.x;
    if (t >= N_TOK) return;
    float hs = g_hs[t];
    for (int s = 0; s < TOPK; s++) {
        int e = g_tok_eidx[t*TOPK + s];
        int p = atomicAdd(&g_cursor[e], 1);
        g_pair_token[p] = t;
        g_pair_gate[p]  = g_tok_gate[t*TOPK + s];
        g_ags[p]        = hs;
        g_pairpos[t*TOPK + s] = p;
    }
}

__global__ __launch_bounds__(256) void gather_kernel() {
    int idx = blockIdx.x * 256 + threadIdx.x;     // PAIR_CAP * (DIM/16) chunks
    if (idx >= PAIR_CAP * (DIM / 16)) return;
    int p = idx >> 5, c = (idx & 31) << 4;
    int t = g_pair_token[p];
    uint4 v1 = make_uint4(0,0,0,0), v2 = v1;
    if (t >= 0) {
        v1 = *(const uint4*)(g_hq1 + (size_t)t * DIM + c);
        v2 = *(const uint4*)(g_hq2 + (size_t)t * DIM + c);
    }
    *(uint4*)(g_agq1 + (size_t)p * DIM + c) = v1;
    *(uint4*)(g_agq2 + (size_t)p * DIM + c) = v2;
}

__global__ __launch_bounds__(256) void combine_kernel(float* __restrict__ out, int accumulate)
{
    int idx = blockIdx.x * 256 + threadIdx.x;
    if (idx >= N_TOK * (DIM/4)) return;
    int t = idx >> 7, d = (idx & 127) << 2;
    float4 acc;
    if (accumulate) acc = *(float4*)(out + (size_t)t * DIM + d);
    else            acc = make_float4(0.f, 0.f, 0.f, 0.f);
#pragma unroll
    for (int s = 0; s < TOPK; s++) {
        int p = g_pairpos[t*TOPK + s];
        float4 v = *(const float4*)(g_slot + (size_t)p * DIM + d);
        acc.x += v.x; acc.y += v.y; acc.z += v.z; acc.w += v.w;
    }
    *(float4*)(out + (size_t)t * DIM + d) = acc;
}

// ---------------- host -----------------------------------------------------
extern "C" void kernel_launch(void* const* d_in, const int* in_sizes, int n_in,
                              void* d_out, int out_size)
{
    const float* view[2]  = {(const float*)d_in[0], (const float*)d_in[1]};
    const float* proj_w   = (const float*)d_in[2];
    const float* proj_b   = (const float*)d_in[3];
    const float* router_w = (const float*)d_in[4];
    const float* keys     = (const float*)d_in[5];
    const float* w1       = (const float*)d_in[6];
    const float* b1       = (const float*)d_in[7];
    const float* w2       = (const float*)d_in[8];
    const float* b2       = (const float*)d_in[9];
    float* out = (float*)d_out;

    void *xq1,*xq2,*xs,*hq1,*hq2,*hs,*agq1,*agq2,*ags,*hidq1,*hidq2,*hids;
    void *pwq1,*pwq2,*pwt,*rwq1,*rwq2,*rwt,*w1q1,*w1q2,*w1t,*w2q1,*w2q2,*w2t;
    void *hbuf,*hidbuf;
    cudaGetSymbolAddress(&xq1, g_xq1);   cudaGetSymbolAddress(&xq2, g_xq2);
    cudaGetSymbolAddress(&xs,  g_xs);
    cudaGetSymbolAddress(&hq1, g_hq1);   cudaGetSymbolAddress(&hq2, g_hq2);
    cudaGetSymbolAddress(&hs,  g_hs);    cudaGetSymbolAddress(&hbuf, g_h);
    cudaGetSymbolAddress(&agq1, g_agq1); cudaGetSymbolAddress(&agq2, g_agq2);
    cudaGetSymbolAddress(&ags, g_ags);
    cudaGetSymbolAddress(&hidq1, g_hidq1); cudaGetSymbolAddress(&hidq2, g_hidq2);
    cudaGetSymbolAddress(&hids, g_hids); cudaGetSymbolAddress(&hidbuf, g_hid);
    cudaGetSymbolAddress(&pwq1, g_pwq1); cudaGetSymbolAddress(&pwq2, g_pwq2);
    cudaGetSymbolAddress(&pwt,  g_pwt);
    cudaGetSymbolAddress(&rwq1, g_rwq1); cudaGetSymbolAddress(&rwq2, g_rwq2);
    cudaGetSymbolAddress(&rwt,  g_rwt);
    cudaGetSymbolAddress(&w1q1, g_w1q1); cudaGetSymbolAddress(&w1q2, g_w1q2);
    cudaGetSymbolAddress(&w1t,  g_w1t);
    cudaGetSymbolAddress(&w2q1, g_w2q1); cudaGetSymbolAddress(&w2q2, g_w2q2);
    cudaGetSymbolAddress(&w2t,  g_w2t);

    cudaFuncSetAttribute((const void*)imma_gemm_kernel<0,512,512>,
                         cudaFuncAttributeMaxDynamicSharedMemorySize, SMEM_DYN);
    cudaFuncSetAttribute((const void*)imma_gemm_kernel<1,512,512>,
                         cudaFuncAttributeMaxDynamicSharedMemorySize, SMEM_DYN);
    cudaFuncSetAttribute((const void*)imma_gemm_kernel<2,512,2048>,
                         cudaFuncAttributeMaxDynamicSharedMemorySize, SMEM_DYN);
    cudaFuncSetAttribute((const void*)imma_gemm_kernel<3,2048,512>,
                         cudaFuncAttributeMaxDynamicSharedMemorySize, SMEM_DYN);

    // ---- weight quantization (transposed limbs + col scales) ----
    dim3 tqb(32, 8);
    colmax_kernel<<<dim3(DIM/256, 2), 256>>>(proj_w, (float*)pwt, DIM, DIM);
    tq_kernel<<<dim3(DIM/32, DIM/32, 2), tqb>>>(proj_w, (const float*)pwt,
        (int8_t*)pwq1, (int8_t*)pwq2, DIM, DIM);
    colmax_kernel<<<dim3(DIM/256, 2), 256>>>(router_w, (float*)rwt, DIM, DIM);
    tq_kernel<<<dim3(DIM/32, DIM/32, 2), tqb>>>(router_w, (const float*)rwt,
        (int8_t*)rwq1, (int8_t*)rwq2, DIM, DIM);
    colmax_kernel<<<dim3(HID/256, N_EXP), 256>>>(w1, (float*)w1t, DIM, HID);
    tq_kernel<<<dim3(HID/32, DIM/32, N_EXP), tqb>>>(w1, (const float*)w1t,
        (int8_t*)w1q1, (int8_t*)w1q2, DIM, HID);
    colmax_kernel<<<dim3(DIM/256, N_EXP), 256>>>(w2, (float*)w2t, HID, DIM);
    tq_kernel<<<dim3(DIM/32, HID/32, N_EXP), tqb>>>(w2, (const float*)w2t,
        (int8_t*)w2q1, (int8_t*)w2q2, HID, DIM);

    dim3 gpr(DIM/128, N_TOK/128);        // (4, 32)
    dim3 gf1(HID/128, MAX_T128);         // (16, 144)
    dim3 gf2(DIM/128, MAX_T128);         // (4, 144)

    for (int v = 0; v < 2; v++) {
        quant_rows_kernel<DIM><<<N_TOK, 128>>>(view[v],
            (int8_t*)xq1, (int8_t*)xq2, (float*)xs);
        imma_gemm_kernel<0,512,512><<<gpr, 256, SMEM_DYN>>>(
            (const int8_t*)xq1, (const int8_t*)xq2, (const float*)xs,
            (const int8_t*)pwq1, (const int8_t*)pwq2, (const float*)pwt, proj_b, v);
        quant_rows_kernel<DIM><<<N_TOK, 128>>>((const float*)hbuf,
            (int8_t*)hq1, (int8_t*)hq2, (float*)hs);
        imma_gemm_kernel<1,512,512><<<gpr, 256, SMEM_DYN>>>(
            (const int8_t*)hq1, (const int8_t*)hq2, (const float*)hs,
            (const int8_t*)rwq1, (const int8_t*)rwq2, (const float*)rwt, nullptr, v);
        reset_kernel<<<(PAIR_CAP+255)/256, 256>>>();
        gate_kernel<<<N_TOK, 128>>>(keys);
        scan_kernel<<<1, 1>>>();
        scatter_kernel<<<N_TOK/128, 128>>>();
        gather_kernel<<<(PAIR_CAP*(DIM/16)+255)/256, 256>>>();
        imma_gemm_kernel<2,512,2048><<<gf1, 256, SMEM_DYN>>>(
            (const int8_t*)agq1, (const int8_t*)agq2, (const float*)ags,
            (const int8_t*)w1q1, (const int8_t*)w1q2, (const float*)w1t, b1, 0);
        quant_rows_kernel<HID><<<PAIR_CAP, 128>>>((const float*)hidbuf,
            (int8_t*)hidq1, (int8_t*)hidq2, (float*)hids);
        imma_gemm_kernel<3,2048,512><<<gf2, 256, SMEM_DYN>>>(
            (const int8_t*)hidq1, (const int8_t*)hidq2, (const float*)hids,
            (const int8_t*)w2q1, (const int8_t*)w2q2, (const float*)w2t, b2, 0);
        combine_kernel<<<(N_TOK*(DIM/4)+255)/256, 256>>>(out, v);
    }
}

// round 9
// speedup vs baseline: 4.5766x; 4.5766x over previous
#include <cuda_runtime.h>
#include <cuda_fp16.h>
#include <math.h>
#include <stdint.h>

#define N_TOK    4096
#define DIM      512
#define N_EXP    16
#define TOPK     4
#define HID      2048
#define PAIR_CAP 20480
#define MAX_T256 80
#define MAX_T128 160

// ---------------- device scratch -------------------------------------------
__device__ __half g_x_hi [N_TOK * DIM];
__device__ __half g_x_lo [N_TOK * DIM];
__device__ __half g_h_hi [N_TOK * DIM];
__device__ __half g_h_lo [N_TOK * DIM];
__device__ float  g_r    [N_TOK * DIM];
__device__ __half g_pw [2 * DIM * DIM];
__device__ __half g_rw [2 * DIM * DIM];
__device__ __half g_w1 [N_EXP * DIM * HID];
__device__ __half g_w2 [N_EXP * HID * DIM];
__device__ __half g_hid [(size_t)PAIR_CAP * HID];
__device__ float  g_slot[(size_t)PAIR_CAP * DIM];

__device__ int   g_pair_token[PAIR_CAP];
__device__ float g_pair_gate [PAIR_CAP];
__device__ int   g_pairpos [N_TOK * TOPK];
__device__ int   g_tok_eidx[N_TOK * TOPK];
__device__ float g_tok_gate[N_TOK * TOPK];
__device__ int   g_counts [N_EXP];
__device__ int   g_offsets[N_EXP + 1];
__device__ int   g_cursor [N_EXP];
__device__ int   g_t256_e [MAX_T256];
__device__ int   g_t256_m0[MAX_T256];
__device__ int   g_t128_e [MAX_T128];
__device__ int   g_t128_m0[MAX_T128];
__device__ int   g_nt256, g_nt128;

// ---------------- asm helpers ----------------------------------------------
__device__ __forceinline__ uint32_t smem_u32(const void* p) {
    uint32_t a;
    asm("{ .reg .u64 t; cvta.to.shared.u64 t, %1; cvt.u32.u64 %0, t; }" : "=r"(a) : "l"(p));
    return a;
}
__device__ __forceinline__ void cpa16(uint32_t s, const void* g) {
    asm volatile("cp.async.cg.shared.global [%0], [%1], 16;" :: "r"(s), "l"(g));
}
#define CP_COMMIT() asm volatile("cp.async.commit_group;" ::: "memory")
#define CP_WAIT(n)  asm volatile("cp.async.wait_group %0;" :: "n"(n) : "memory")

__device__ __forceinline__ void ldm_x4(uint32_t* r, uint32_t a) {
    asm volatile("ldmatrix.sync.aligned.m8n8.x4.shared.b16 {%0,%1,%2,%3}, [%4];"
        : "=r"(r[0]), "=r"(r[1]), "=r"(r[2]), "=r"(r[3]) : "r"(a));
}
__device__ __forceinline__ void ldm_x4_t(uint32_t* r, uint32_t a) {
    asm volatile("ldmatrix.sync.aligned.m8n8.x4.trans.shared.b16 {%0,%1,%2,%3}, [%4];"
        : "=r"(r[0]), "=r"(r[1]), "=r"(r[2]), "=r"(r[3]) : "r"(a));
}
__device__ __forceinline__ void mma_fp16(float* d, const uint32_t* a, uint32_t b0, uint32_t b1) {
    asm volatile("mma.sync.aligned.m16n8k16.row.col.f32.f16.f16.f32 "
        "{%0,%1,%2,%3}, {%4,%5,%6,%7}, {%8,%9}, {%0,%1,%2,%3};"
        : "+f"(d[0]), "+f"(d[1]), "+f"(d[2]), "+f"(d[3])
        : "r"(a[0]), "r"(a[1]), "r"(a[2]), "r"(a[3]), "r"(b0), "r"(b1));
}
__device__ __forceinline__ float gelu_exact(float x) {
    return 0.5f * x * (1.0f + erff(x * 0.70710678118654752440f));
}

// ---------------- HMMA GEMM ------------------------------------------------
// A row-major fp16 (ALIMB limbs), B row-major fp16 [K][N] (ldmatrix.trans).
// 8 warps, 64x64 warp tiles, 3-stage cp.async pipeline.
// MODE 0: proj (+bias -> g_h hi/lo)  1: router (-> g_r)
// MODE 2: ffn1, indirect A rows via token table (+bias,gelu -> g_hid fp16)
// MODE 3: ffn2 (+bias,*gate -> g_slot)
template<int MODE, int KLEN, int NTOT, int BM, int BN, int ALIMB>
__global__ __launch_bounds__(256, 1) void mma_gemm_kernel(
    const __half* __restrict__ Ah, const __half* __restrict__ Al,
    const __half* __restrict__ B,
    const float* __restrict__ bias, int zview)
{
    constexpr int NC   = KLEN / 32;
    constexpr int PB   = BN * 2 + 16;
    constexpr int ABY  = BM * 80;
    constexpr int BOFF = ALIMB * ABY;
    constexpr int STG  = ALIMB * ABY + 32 * PB;
    constexpr int WR   = BM / 64;

    int n0 = blockIdx.x * BN, m0, z;
    if (MODE <= 1) { m0 = blockIdx.y * BM; z = zview; }
    else if (MODE == 2) {
        if ((int)blockIdx.y >= g_nt256) return;
        z = g_t256_e[blockIdx.y]; m0 = g_t256_m0[blockIdx.y];
    } else {
        if ((int)blockIdx.y >= g_nt128) return;
        z = g_t128_e[blockIdx.y]; m0 = g_t128_m0[blockIdx.y];
    }
    const __half* Bz = B + (size_t)z * KLEN * NTOT;

    extern __shared__ __align__(16) char smem[];
    uint32_t sb = smem_u32(smem);

    const int tid = threadIdx.x, lane = tid & 31, warp = tid >> 5;
    const int mw = (warp % WR) * 64, nw = (warp / WR) * 64;
    const int lr = lane & 15, lc = (lane >> 4) << 3;

    int* tok = (int*)(smem + 3 * STG);
    if (MODE == 2) {
        if (tid < BM) {
            int t = g_pair_token[m0 + tid];
            tok[tid] = t < 0 ? 0 : t;
        }
        __syncthreads();
    }

    auto load_stage = [&](int s, int c) {
        const int k0 = c * 32;
        const uint32_t base = sb + (uint32_t)s * STG;
#pragma unroll
        for (int ch = tid; ch < BM * 4; ch += 256) {
            int row = ch >> 2, kc = ch & 3;
            const __half* src;
            if (MODE == 2) src = Ah + (size_t)tok[row] * KLEN + k0 + kc * 8;
            else           src = Ah + (size_t)(m0 + row) * KLEN + k0 + kc * 8;
            cpa16(base + row * 80 + kc * 16, src);
            if (ALIMB == 2)
                cpa16(base + ABY + row * 80 + kc * 16,
                      Al + (size_t)(m0 + row) * KLEN + k0 + kc * 8);
        }
#pragma unroll
        for (int ch = tid; ch < BN * 4; ch += 256) {
            int row = ch / (BN / 8), nc = ch % (BN / 8);
            cpa16(base + BOFF + row * PB + nc * 16,
                  Bz + (size_t)(k0 + row) * NTOT + n0 + nc * 8);
        }
    };

    float acc[4][8][4];
#pragma unroll
    for (int a = 0; a < 4; a++)
#pragma unroll
        for (int b = 0; b < 8; b++)
#pragma unroll
            for (int d = 0; d < 4; d++) acc[a][b][d] = 0.f;

    load_stage(0, 0); CP_COMMIT();
    if (NC > 1) { load_stage(1, 1); CP_COMMIT(); }

    for (int c = 0; c < NC; c++) {
        if (c + 2 < NC) { load_stage((c + 2) % 3, c + 2); CP_COMMIT(); CP_WAIT(2); }
        else if (c + 1 < NC) CP_WAIT(1);
        else CP_WAIT(0);
        __syncthreads();

        const uint32_t base = sb + (uint32_t)(c % 3) * STG;
#pragma unroll
        for (int ks = 0; ks < 2; ks++) {
            uint32_t a1[4][4], a2[4][4];
#pragma unroll
            for (int ms = 0; ms < 4; ms++) {
                uint32_t ad = base + (uint32_t)((mw + ms * 16 + lr) * 80 + (ks * 16 + lc) * 2);
                ldm_x4(a1[ms], ad);
                if (ALIMB == 2) ldm_x4(a2[ms], ad + ABY);
            }
#pragma unroll
            for (int np = 0; np < 4; np++) {
                uint32_t bf[4];
                uint32_t bd = base + BOFF + (uint32_t)((ks * 16 + lr) * PB + (nw + np * 16 + lc) * 2);
                ldm_x4_t(bf, bd);
#pragma unroll
                for (int ms = 0; ms < 4; ms++)
#pragma unroll
                    for (int sub = 0; sub < 2; sub++) {
                        int ns = np * 2 + sub;
                        mma_fp16(acc[ms][ns], a1[ms], bf[sub*2], bf[sub*2+1]);
                        if (ALIMB == 2)
                            mma_fp16(acc[ms][ns], a2[ms], bf[sub*2], bf[sub*2+1]);
                    }
            }
        }
        __syncthreads();
    }

    // ---- epilogue ----
    const int lrow = lane >> 2, lcol = (lane & 3) * 2;
#pragma unroll
    for (int ms = 0; ms < 4; ms++) {
        int r0 = m0 + mw + ms * 16 + lrow;
        float gt0 = 0.f, gt1 = 0.f;
        if (MODE == 3) { gt0 = g_pair_gate[r0]; gt1 = g_pair_gate[r0 + 8]; }
#pragma unroll
        for (int ns = 0; ns < 8; ns++) {
            int cc = n0 + nw + ns * 8 + lcol;
            float b0 = 0.f, b1 = 0.f;
            if (MODE != 1) {
                b0 = bias[(size_t)z * NTOT + cc];
                b1 = bias[(size_t)z * NTOT + cc + 1];
            }
            float v00 = acc[ms][ns][0] + b0, v01 = acc[ms][ns][1] + b1;
            float v10 = acc[ms][ns][2] + b0, v11 = acc[ms][ns][3] + b1;
            if (MODE == 2) {
                v00 = gelu_exact(v00); v01 = gelu_exact(v01);
                v10 = gelu_exact(v10); v11 = gelu_exact(v11);
            }
            if (MODE == 3) { v00 *= gt0; v01 *= gt0; v10 *= gt1; v11 *= gt1; }
            if (MODE == 1 || MODE == 3) {
                float* OUT = (MODE == 1) ? g_r : g_slot;
                *(float2*)(OUT + (size_t)r0 * NTOT + cc)       = make_float2(v00, v01);
                *(float2*)(OUT + (size_t)(r0 + 8) * NTOT + cc) = make_float2(v10, v11);
            } else if (MODE == 2) {
                *(__half2*)(g_hid + (size_t)r0 * NTOT + cc) =
                    __halves2half2(__float2half(v00), __float2half(v01));
                *(__half2*)(g_hid + (size_t)(r0 + 8) * NTOT + cc) =
                    __halves2half2(__float2half(v10), __float2half(v11));
            } else {
                __half h00 = __float2half(v00), h01 = __float2half(v01);
                __half h10 = __float2half(v10), h11 = __float2half(v11);
                *(__half2*)(g_h_hi + (size_t)r0 * NTOT + cc)       = __halves2half2(h00, h01);
                *(__half2*)(g_h_hi + (size_t)(r0 + 8) * NTOT + cc) = __halves2half2(h10, h11);
                *(__half2*)(g_h_lo + (size_t)r0 * NTOT + cc) =
                    __halves2half2(__float2half(v00 - __half2float(h00)),
                                   __float2half(v01 - __half2float(h01)));
                *(__half2*)(g_h_lo + (size_t)(r0 + 8) * NTOT + cc) =
                    __halves2half2(__float2half(v10 - __half2float(h10)),
                                   __float2half(v11 - __half2float(h11)));
            }
        }
    }
}

// ---------------- small kernels ---------------------------------------------
__global__ __launch_bounds__(256) void split8_kernel(
    const float* __restrict__ in, __half* __restrict__ hi,
    __half* __restrict__ lo, int n)
{
    int i = (blockIdx.x * 256 + threadIdx.x) * 8;
    if (i >= n) return;
    float4 a = *(const float4*)(in + i);
    float4 b = *(const float4*)(in + i + 4);
    float v[8] = {a.x, a.y, a.z, a.w, b.x, b.y, b.z, b.w};
    union { __half2 p[4]; uint4 u; } ph, pl;
#pragma unroll
    for (int j = 0; j < 4; j++) {
        __half h0 = __float2half(v[2*j]);
        __half h1 = __float2half(v[2*j+1]);
        ph.p[j] = __halves2half2(h0, h1);
        pl.p[j] = __halves2half2(
            __float2half(v[2*j]   - __half2float(h0)),
            __float2half(v[2*j+1] - __half2float(h1)));
    }
    *(uint4*)(hi + i) = ph.u;
    *(uint4*)(lo + i) = pl.u;
}

__global__ __launch_bounds__(256) void conv8_kernel(
    const float* __restrict__ in, __half* __restrict__ out, int n)
{
    int i = (blockIdx.x * 256 + threadIdx.x) * 8;
    if (i >= n) return;
    float4 a = *(const float4*)(in + i);
    float4 b = *(const float4*)(in + i + 4);
    float v[8] = {a.x, a.y, a.z, a.w, b.x, b.y, b.z, b.w};
    union { __half2 p[4]; uint4 u; } ph;
#pragma unroll
    for (int j = 0; j < 4; j++)
        ph.p[j] = __halves2half2(__float2half(v[2*j]), __float2half(v[2*j+1]));
    *(uint4*)(out + i) = ph.u;
}

// warp-per-token gate: 8 tokens/block, keys staged in smem
__global__ __launch_bounds__(256) void gate_kernel(const float* __restrict__ keys)
{
    __shared__ float ks[N_EXP][DIM];
    const int tid = threadIdx.x;
    for (int i = tid; i < N_EXP * DIM; i += 256)
        ks[i >> 9][i & 511] = keys[i];
    __syncthreads();

    const int warp = tid >> 5, lane = tid & 31;
    const int t = blockIdx.x * 8 + warp;
    const float* rr = g_r + (size_t)t * DIM;
    float rv[16];
#pragma unroll
    for (int j = 0; j < 16; j++) rv[j] = rr[lane + 32 * j];

    float lg[N_EXP];
#pragma unroll
    for (int e = 0; e < N_EXP; e++) {
        float s = 0.f;
#pragma unroll
        for (int j = 0; j < 16; j++) {
            float d = rv[j] - ks[e][lane + 32 * j];
            s = fmaf(d, d, s);
        }
#pragma unroll
        for (int o = 16; o > 0; o >>= 1)
            s += __shfl_xor_sync(0xFFFFFFFF, s, o);
        lg[e] = -sqrtf(fmaxf(s, 0.f));
    }
    if (lane == 0) {
        int idx[TOPK]; float val[TOPK]; bool used[N_EXP];
#pragma unroll
        for (int i = 0; i < N_EXP; i++) used[i] = false;
        for (int s2 = 0; s2 < TOPK; s2++) {
            int bi = -1; float bv = -1e30f;
            for (int i = 0; i < N_EXP; i++)
                if (!used[i] && lg[i] > bv) { bv = lg[i]; bi = i; }
            used[bi] = true; idx[s2] = bi; val[s2] = bv;
        }
        float mx = val[0], ex[TOPK], se = 0.f;
        for (int s2 = 0; s2 < TOPK; s2++) { ex[s2] = expf(val[s2] - mx); se += ex[s2]; }
        float inv = 1.0f / se;
        for (int s2 = 0; s2 < TOPK; s2++) {
            g_tok_eidx[t*TOPK + s2] = idx[s2];
            g_tok_gate[t*TOPK + s2] = ex[s2] * inv;
            atomicAdd(&g_counts[idx[s2]], 1);
        }
    }
}

__global__ void reset_kernel() {
    if (threadIdx.x < N_EXP) g_counts[threadIdx.x] = 0;
}

__global__ void scan_kernel() {
    if (threadIdx.x == 0) {
        int o = 0, n256 = 0, n128 = 0;
        for (int e = 0; e < N_EXP; e++) {
            g_offsets[e] = o; g_cursor[e] = o;
            int seg = ((g_counts[e] + 255) >> 8) << 8;
            for (int i = 0; i < seg / 256; i++) { g_t256_e[n256] = e; g_t256_m0[n256] = o + i * 256; n256++; }
            for (int i = 0; i < seg / 128; i++) { g_t128_e[n128] = e; g_t128_m0[n128] = o + i * 128; n128++; }
            o += seg;
        }
        g_offsets[N_EXP] = o;
        g_nt256 = n256; g_nt128 = n128;
    }
}

__global__ __launch_bounds__(128) void scatter_kernel() {
    int t = blockIdx.x * 128 + threadIdx.x;
    if (t >= N_TOK) return;
    for (int s = 0; s < TOPK; s++) {
        int e = g_tok_eidx[t*TOPK + s];
        int p = atomicAdd(&g_cursor[e], 1);
        g_pair_token[p] = t;
        g_pair_gate[p]  = g_tok_gate[t*TOPK + s];
        g_pairpos[t*TOPK + s] = p;
    }
}

__global__ __launch_bounds__(256) void combine_kernel(float* __restrict__ out, int accumulate)
{
    int idx = blockIdx.x * 256 + threadIdx.x;
    if (idx >= N_TOK * (DIM/4)) return;
    int t = idx >> 7, d = (idx & 127) << 2;
    float4 acc;
    if (accumulate) acc = *(float4*)(out + (size_t)t * DIM + d);
    else            acc = make_float4(0.f, 0.f, 0.f, 0.f);
#pragma unroll
    for (int s = 0; s < TOPK; s++) {
        int p = g_pairpos[t*TOPK + s];
        float4 v = *(const float4*)(g_slot + (size_t)p * DIM + d);
        acc.x += v.x; acc.y += v.y; acc.z += v.z; acc.w += v.w;
    }
    *(float4*)(out + (size_t)t * DIM + d) = acc;
}

// ---------------- host -----------------------------------------------------
#define STG_OF(BM, BN, AL) ((AL) * (BM) * 80 + 32 * ((BN) * 2 + 16))

extern "C" void kernel_launch(void* const* d_in, const int* in_sizes, int n_in,
                              void* d_out, int out_size)
{
    const float* view[2]  = {(const float*)d_in[0], (const float*)d_in[1]};
    const float* proj_w   = (const float*)d_in[2];
    const float* proj_b   = (const float*)d_in[3];
    const float* router_w = (const float*)d_in[4];
    const float* keys     = (const float*)d_in[5];
    const float* w1       = (const float*)d_in[6];
    const float* b1       = (const float*)d_in[7];
    const float* w2       = (const float*)d_in[8];
    const float* b2       = (const float*)d_in[9];
    float* out = (float*)d_out;

    void *xhi,*xlo,*hhi,*hlo,*pw,*rw,*w1p,*w2p,*hid;
    cudaGetSymbolAddress(&xhi, g_x_hi);  cudaGetSymbolAddress(&xlo, g_x_lo);
    cudaGetSymbolAddress(&hhi, g_h_hi);  cudaGetSymbolAddress(&hlo, g_h_lo);
    cudaGetSymbolAddress(&pw, g_pw);     cudaGetSymbolAddress(&rw, g_rw);
    cudaGetSymbolAddress(&w1p, g_w1);    cudaGetSymbolAddress(&w2p, g_w2);
    cudaGetSymbolAddress(&hid, g_hid);

    constexpr int SM_PR = 3 * STG_OF(128, 256, 2);          // 112128
    constexpr int SM_F1 = 3 * STG_OF(256, 128, 1) + 1024;   // 88576
    constexpr int SM_F2 = 3 * STG_OF(128, 256, 1);          // 81408
    cudaFuncSetAttribute((const void*)mma_gemm_kernel<0,512,512,128,256,2>,
                         cudaFuncAttributeMaxDynamicSharedMemorySize, SM_PR);
    cudaFuncSetAttribute((const void*)mma_gemm_kernel<1,512,512,128,256,2>,
                         cudaFuncAttributeMaxDynamicSharedMemorySize, SM_PR);
    cudaFuncSetAttribute((const void*)mma_gemm_kernel<2,512,2048,256,128,1>,
                         cudaFuncAttributeMaxDynamicSharedMemorySize, SM_F1);
    cudaFuncSetAttribute((const void*)mma_gemm_kernel<3,2048,512,128,256,1>,
                         cudaFuncAttributeMaxDynamicSharedMemorySize, SM_F2);

    conv8_kernel<<<(2*DIM*DIM/8+255)/256, 256>>>(proj_w,   (__half*)pw,  2*DIM*DIM);
    conv8_kernel<<<(2*DIM*DIM/8+255)/256, 256>>>(router_w, (__half*)rw,  2*DIM*DIM);
    conv8_kernel<<<(N_EXP*DIM*HID/8+255)/256, 256>>>(w1,   (__half*)w1p, N_EXP*DIM*HID);
    conv8_kernel<<<(N_EXP*HID*DIM/8+255)/256, 256>>>(w2,   (__half*)w2p, N_EXP*HID*DIM);

    dim3 gpr(DIM/256, N_TOK/128);        // (2, 32)
    dim3 gf1(HID/128, MAX_T256);         // (16, 80)
    dim3 gf2(DIM/256, MAX_T128);         // (2, 160)

    for (int v = 0; v < 2; v++) {
        split8_kernel<<<(N_TOK*DIM/8+255)/256, 256>>>(view[v],
            (__half*)xhi, (__half*)xlo, N_TOK*DIM);
        mma_gemm_kernel<0,512,512,128,256,2><<<gpr, 256, SM_PR>>>(
            (const __half*)xhi, (const __half*)xlo, (const __half*)pw, proj_b, v);
        mma_gemm_kernel<1,512,512,128,256,2><<<gpr, 256, SM_PR>>>(
            (const __half*)hhi, (const __half*)hlo, (const __half*)rw, nullptr, v);
        reset_kernel<<<1, 32>>>();
        gate_kernel<<<N_TOK/8, 256>>>(keys);
        scan_kernel<<<1, 1>>>();
        scatter_kernel<<<N_TOK/128, 128>>>();
        mma_gemm_kernel<2,512,2048,256,128,1><<<gf1, 256, SM_F1>>>(
            (const __half*)hhi, nullptr, (const __half*)w1p, b1, 0);
        mma_gemm_kernel<3,2048,512,128,256,1><<<gf2, 256, SM_F2>>>(
            (const __half*)hid, nullptr, (const __half*)w2p, b2, 0);
        combine_kernel<<<(N_TOK*(DIM/4)+255)/256, 256>>>(out, v);
    }
}

// round 10
// speedup vs baseline: 5.1820x; 1.1323x over previous
#include <cuda_runtime.h>
#include <cuda_fp16.h>
#include <math.h>
#include <stdint.h>

#define N_TOK    4096
#define N_TOKV   8192            // both views batched
#define DIM      512
#define N_EXP    16
#define TOPK     4
#define HID      2048
#define PAIR_CAP 36864           // 32768 pairs + 16 experts * 256 pad
#define MAX_T256 160
#define MAX_T128 320

// ---------------- device scratch -------------------------------------------
__device__ __half g_x_hi [N_TOKV * DIM];
__device__ __half g_x_lo [N_TOKV * DIM];
__device__ __half g_h_hi [N_TOKV * DIM];
__device__ __half g_h_lo [N_TOKV * DIM];
__device__ float  g_r    [N_TOKV * DIM];
__device__ __half g_pw [2 * DIM * DIM];
__device__ __half g_rw [2 * DIM * DIM];
__device__ __half g_w1 [N_EXP * DIM * HID];
__device__ __half g_w2 [N_EXP * HID * DIM];
__device__ __half g_hid [(size_t)PAIR_CAP * HID];
__device__ float  g_slot[(size_t)PAIR_CAP * DIM];

__device__ int   g_pair_token[PAIR_CAP];      // zero-init: always valid row idx
__device__ float g_pair_gate [PAIR_CAP];
__device__ int   g_pairpos [N_TOKV * TOPK];
__device__ int   g_tok_eidx[N_TOKV * TOPK];
__device__ float g_tok_gate[N_TOKV * TOPK];
__device__ int   g_counts [N_EXP];
__device__ int   g_offsets[N_EXP + 1];
__device__ int   g_cursor [N_EXP];
__device__ int   g_t256_e [MAX_T256];
__device__ int   g_t256_m0[MAX_T256];
__device__ int   g_t128_e [MAX_T128];
__device__ int   g_t128_m0[MAX_T128];
__device__ int   g_nt256, g_nt128;

// ---------------- asm helpers ----------------------------------------------
__device__ __forceinline__ uint32_t smem_u32(const void* p) {
    uint32_t a;
    asm("{ .reg .u64 t; cvta.to.shared.u64 t, %1; cvt.u32.u64 %0, t; }" : "=r"(a) : "l"(p));
    return a;
}
__device__ __forceinline__ void cpa16(uint32_t s, const void* g) {
    asm volatile("cp.async.cg.shared.global [%0], [%1], 16;" :: "r"(s), "l"(g));
}
#define CP_COMMIT() asm volatile("cp.async.commit_group;" ::: "memory")
#define CP_WAIT(n)  asm volatile("cp.async.wait_group %0;" :: "n"(n) : "memory")

__device__ __forceinline__ void ldm_x4(uint32_t* r, uint32_t a) {
    asm volatile("ldmatrix.sync.aligned.m8n8.x4.shared.b16 {%0,%1,%2,%3}, [%4];"
        : "=r"(r[0]), "=r"(r[1]), "=r"(r[2]), "=r"(r[3]) : "r"(a));
}
__device__ __forceinline__ void ldm_x4_t(uint32_t* r, uint32_t a) {
    asm volatile("ldmatrix.sync.aligned.m8n8.x4.trans.shared.b16 {%0,%1,%2,%3}, [%4];"
        : "=r"(r[0]), "=r"(r[1]), "=r"(r[2]), "=r"(r[3]) : "r"(a));
}
__device__ __forceinline__ void mma_fp16(float* d, const uint32_t* a, uint32_t b0, uint32_t b1) {
    asm volatile("mma.sync.aligned.m16n8k16.row.col.f32.f16.f16.f32 "
        "{%0,%1,%2,%3}, {%4,%5,%6,%7}, {%8,%9}, {%0,%1,%2,%3};"
        : "+f"(d[0]), "+f"(d[1]), "+f"(d[2]), "+f"(d[3])
        : "r"(a[0]), "r"(a[1]), "r"(a[2]), "r"(a[3]), "r"(b0), "r"(b1));
}
__device__ __forceinline__ float gelu_exact(float x) {
    return 0.5f * x * (1.0f + erff(x * 0.70710678118654752440f));
}

// ---------------- HMMA GEMM ------------------------------------------------
// A row-major fp16 (ALIMB limbs), B row-major fp16 [K][N] (ldmatrix.trans).
// 8 warps, 64x64 warp tiles, 3-stage cp.async pipeline.
// MODE 0: proj  (z = view from m0; +bias -> g_h hi/lo)
// MODE 1: router(z = view from m0; -> g_r)
// MODE 2: ffn1  (indirect A rows; +bias,gelu -> g_hid fp16)
// MODE 3: ffn2  (+bias,*gate -> g_slot)
template<int MODE, int KLEN, int NTOT, int BM, int BN, int ALIMB>
__global__ __launch_bounds__(256, 1) void mma_gemm_kernel(
    const __half* __restrict__ Ah, const __half* __restrict__ Al,
    const __half* __restrict__ B,
    const float* __restrict__ bias)
{
    constexpr int NC   = KLEN / 32;
    constexpr int PB   = BN * 2 + 16;
    constexpr int ABY  = BM * 80;
    constexpr int BOFF = ALIMB * ABY;
    constexpr int STG  = ALIMB * ABY + 32 * PB;
    constexpr int WR   = BM / 64;

    int n0 = blockIdx.x * BN, m0, z;
    if (MODE <= 1) { m0 = blockIdx.y * BM; z = (m0 >= N_TOK) ? 1 : 0; }
    else if (MODE == 2) {
        if ((int)blockIdx.y >= g_nt256) return;
        z = g_t256_e[blockIdx.y]; m0 = g_t256_m0[blockIdx.y];
    } else {
        if ((int)blockIdx.y >= g_nt128) return;
        z = g_t128_e[blockIdx.y]; m0 = g_t128_m0[blockIdx.y];
    }
    const __half* Bz = B + (size_t)z * KLEN * NTOT;

    extern __shared__ __align__(16) char smem[];
    uint32_t sb = smem_u32(smem);

    const int tid = threadIdx.x, lane = tid & 31, warp = tid >> 5;
    const int mw = (warp % WR) * 64, nw = (warp / WR) * 64;
    const int lr = lane & 15, lc = (lane >> 4) << 3;

    int* tok = (int*)(smem + 3 * STG);
    if (MODE == 2) {
        if (tid < BM) tok[tid] = g_pair_token[m0 + tid];
        __syncthreads();
    }

    auto load_stage = [&](int s, int c) {
        const int k0 = c * 32;
        const uint32_t base = sb + (uint32_t)s * STG;
#pragma unroll
        for (int ch = tid; ch < BM * 4; ch += 256) {
            int row = ch >> 2, kc = ch & 3;
            const __half* src;
            if (MODE == 2) src = Ah + (size_t)tok[row] * KLEN + k0 + kc * 8;
            else           src = Ah + (size_t)(m0 + row) * KLEN + k0 + kc * 8;
            cpa16(base + row * 80 + kc * 16, src);
            if (ALIMB == 2)
                cpa16(base + ABY + row * 80 + kc * 16,
                      Al + (size_t)(m0 + row) * KLEN + k0 + kc * 8);
        }
#pragma unroll
        for (int ch = tid; ch < BN * 4; ch += 256) {
            int row = ch / (BN / 8), nc = ch % (BN / 8);
            cpa16(base + BOFF + row * PB + nc * 16,
                  Bz + (size_t)(k0 + row) * NTOT + n0 + nc * 8);
        }
    };

    float acc[4][8][4];
#pragma unroll
    for (int a = 0; a < 4; a++)
#pragma unroll
        for (int b = 0; b < 8; b++)
#pragma unroll
            for (int d = 0; d < 4; d++) acc[a][b][d] = 0.f;

    load_stage(0, 0); CP_COMMIT();
    if (NC > 1) { load_stage(1, 1); CP_COMMIT(); }

    for (int c = 0; c < NC; c++) {
        if (c + 2 < NC) { load_stage((c + 2) % 3, c + 2); CP_COMMIT(); CP_WAIT(2); }
        else if (c + 1 < NC) CP_WAIT(1);
        else CP_WAIT(0);
        __syncthreads();

        const uint32_t base = sb + (uint32_t)(c % 3) * STG;
#pragma unroll
        for (int ks = 0; ks < 2; ks++) {
            uint32_t a1[4][4], a2[4][4];
#pragma unroll
            for (int ms = 0; ms < 4; ms++) {
                uint32_t ad = base + (uint32_t)((mw + ms * 16 + lr) * 80 + (ks * 16 + lc) * 2);
                ldm_x4(a1[ms], ad);
                if (ALIMB == 2) ldm_x4(a2[ms], ad + ABY);
            }
#pragma unroll
            for (int np = 0; np < 4; np++) {
                uint32_t bf[4];
                uint32_t bd = base + BOFF + (uint32_t)((ks * 16 + lr) * PB + (nw + np * 16 + lc) * 2);
                ldm_x4_t(bf, bd);
#pragma unroll
                for (int ms = 0; ms < 4; ms++)
#pragma unroll
                    for (int sub = 0; sub < 2; sub++) {
                        int ns = np * 2 + sub;
                        mma_fp16(acc[ms][ns], a1[ms], bf[sub*2], bf[sub*2+1]);
                        if (ALIMB == 2)
                            mma_fp16(acc[ms][ns], a2[ms], bf[sub*2], bf[sub*2+1]);
                    }
            }
        }
        __syncthreads();
    }

    // ---- epilogue ----
    const int lrow = lane >> 2, lcol = (lane & 3) * 2;
#pragma unroll
    for (int ms = 0; ms < 4; ms++) {
        int r0 = m0 + mw + ms * 16 + lrow;
        float gt0 = 0.f, gt1 = 0.f;
        if (MODE == 3) { gt0 = g_pair_gate[r0]; gt1 = g_pair_gate[r0 + 8]; }
#pragma unroll
        for (int ns = 0; ns < 8; ns++) {
            int cc = n0 + nw + ns * 8 + lcol;
            float b0 = 0.f, b1 = 0.f;
            if (MODE != 1) {
                b0 = bias[(size_t)z * NTOT + cc];
                b1 = bias[(size_t)z * NTOT + cc + 1];
            }
            float v00 = acc[ms][ns][0] + b0, v01 = acc[ms][ns][1] + b1;
            float v10 = acc[ms][ns][2] + b0, v11 = acc[ms][ns][3] + b1;
            if (MODE == 2) {
                v00 = gelu_exact(v00); v01 = gelu_exact(v01);
                v10 = gelu_exact(v10); v11 = gelu_exact(v11);
            }
            if (MODE == 3) { v00 *= gt0; v01 *= gt0; v10 *= gt1; v11 *= gt1; }
            if (MODE == 1 || MODE == 3) {
                float* OUT = (MODE == 1) ? g_r : g_slot;
                *(float2*)(OUT + (size_t)r0 * NTOT + cc)       = make_float2(v00, v01);
                *(float2*)(OUT + (size_t)(r0 + 8) * NTOT + cc) = make_float2(v10, v11);
            } else if (MODE == 2) {
                *(__half2*)(g_hid + (size_t)r0 * NTOT + cc) =
                    __halves2half2(__float2half(v00), __float2half(v01));
                *(__half2*)(g_hid + (size_t)(r0 + 8) * NTOT + cc) =
                    __halves2half2(__float2half(v10), __float2half(v11));
            } else {
                __half h00 = __float2half(v00), h01 = __float2half(v01);
                __half h10 = __float2half(v10), h11 = __float2half(v11);
                *(__half2*)(g_h_hi + (size_t)r0 * NTOT + cc)       = __halves2half2(h00, h01);
                *(__half2*)(g_h_hi + (size_t)(r0 + 8) * NTOT + cc) = __halves2half2(h10, h11);
                *(__half2*)(g_h_lo + (size_t)r0 * NTOT + cc) =
                    __halves2half2(__float2half(v00 - __half2float(h00)),
                                   __float2half(v01 - __half2float(h01)));
                *(__half2*)(g_h_lo + (size_t)(r0 + 8) * NTOT + cc) =
                    __halves2half2(__float2half(v10 - __half2float(h10)),
                                   __float2half(v11 - __half2float(h11)));
            }
        }
    }
}

// ---------------- small kernels ---------------------------------------------
__global__ __launch_bounds__(256) void split8_kernel(
    const float* __restrict__ in, __half* __restrict__ hi,
    __half* __restrict__ lo, int n)
{
    int i = (blockIdx.x * 256 + threadIdx.x) * 8;
    if (i >= n) return;
    float4 a = *(const float4*)(in + i);
    float4 b = *(const float4*)(in + i + 4);
    float v[8] = {a.x, a.y, a.z, a.w, b.x, b.y, b.z, b.w};
    union { __half2 p[4]; uint4 u; } ph, pl;
#pragma unroll
    for (int j = 0; j < 4; j++) {
        __half h0 = __float2half(v[2*j]);
        __half h1 = __float2half(v[2*j+1]);
        ph.p[j] = __halves2half2(h0, h1);
        pl.p[j] = __halves2half2(
            __float2half(v[2*j]   - __half2float(h0)),
            __float2half(v[2*j+1] - __half2float(h1)));
    }
    *(uint4*)(hi + i) = ph.u;
    *(uint4*)(lo + i) = pl.u;
}

__global__ __launch_bounds__(256) void conv8_kernel(
    const float* __restrict__ in, __half* __restrict__ out, int n)
{
    int i = (blockIdx.x * 256 + threadIdx.x) * 8;
    if (i >= n) return;
    float4 a = *(const float4*)(in + i);
    float4 b = *(const float4*)(in + i + 4);
    float v[8] = {a.x, a.y, a.z, a.w, b.x, b.y, b.z, b.w};
    union { __half2 p[4]; uint4 u; } ph;
#pragma unroll
    for (int j = 0; j < 4; j++)
        ph.p[j] = __halves2half2(__float2half(v[2*j]), __float2half(v[2*j+1]));
    *(uint4*)(out + i) = ph.u;
}

// warp-per-token gate: 8 tokens/block, keys staged in smem
__global__ __launch_bounds__(256) void gate_kernel(const float* __restrict__ keys)
{
    __shared__ float ks[N_EXP][DIM];
    const int tid = threadIdx.x;
    for (int i = tid; i < N_EXP * DIM; i += 256)
        ks[i >> 9][i & 511] = keys[i];
    __syncthreads();

    const int warp = tid >> 5, lane = tid & 31;
    const int t = blockIdx.x * 8 + warp;
    const float* rr = g_r + (size_t)t * DIM;
    float rv[16];
#pragma unroll
    for (int j = 0; j < 16; j++) rv[j] = rr[lane + 32 * j];

    float lg[N_EXP];
#pragma unroll
    for (int e = 0; e < N_EXP; e++) {
        float s = 0.f;
#pragma unroll
        for (int j = 0; j < 16; j++) {
            float d = rv[j] - ks[e][lane + 32 * j];
            s = fmaf(d, d, s);
        }
#pragma unroll
        for (int o = 16; o > 0; o >>= 1)
            s += __shfl_xor_sync(0xFFFFFFFF, s, o);
        lg[e] = -sqrtf(fmaxf(s, 0.f));
    }
    if (lane == 0) {
        int idx[TOPK]; float val[TOPK]; bool used[N_EXP];
#pragma unroll
        for (int i = 0; i < N_EXP; i++) used[i] = false;
        for (int s2 = 0; s2 < TOPK; s2++) {
            int bi = -1; float bv = -1e30f;
            for (int i = 0; i < N_EXP; i++)
                if (!used[i] && lg[i] > bv) { bv = lg[i]; bi = i; }
            used[bi] = true; idx[s2] = bi; val[s2] = bv;
        }
        float mx = val[0], ex[TOPK], se = 0.f;
        for (int s2 = 0; s2 < TOPK; s2++) { ex[s2] = expf(val[s2] - mx); se += ex[s2]; }
        float inv = 1.0f / se;
        for (int s2 = 0; s2 < TOPK; s2++) {
            g_tok_eidx[t*TOPK + s2] = idx[s2];
            g_tok_gate[t*TOPK + s2] = ex[s2] * inv;
            atomicAdd(&g_counts[idx[s2]], 1);
        }
    }
}

__global__ void reset_kernel() {
    if (threadIdx.x < N_EXP) g_counts[threadIdx.x] = 0;
}

__global__ void scan_kernel() {
    if (threadIdx.x == 0) {
        int o = 0, n256 = 0, n128 = 0;
        for (int e = 0; e < N_EXP; e++) {
            g_offsets[e] = o; g_cursor[e] = o;
            int seg = ((g_counts[e] + 255) >> 8) << 8;
            for (int i = 0; i < seg / 256; i++) { g_t256_e[n256] = e; g_t256_m0[n256] = o + i * 256; n256++; }
            for (int i = 0; i < seg / 128; i++) { g_t128_e[n128] = e; g_t128_m0[n128] = o + i * 128; n128++; }
            o += seg;
        }
        g_offsets[N_EXP] = o;
        g_nt256 = n256; g_nt128 = n128;
    }
}

__global__ __launch_bounds__(128) void scatter_kernel() {
    int t = blockIdx.x * 128 + threadIdx.x;
    if (t >= N_TOKV) return;
    for (int s = 0; s < TOPK; s++) {
        int e = g_tok_eidx[t*TOPK + s];
        int p = atomicAdd(&g_cursor[e], 1);
        g_pair_token[p] = t;
        g_pair_gate[p]  = g_tok_gate[t*TOPK + s];
        g_pairpos[t*TOPK + s] = p;
    }
}

// out[t] = sum over both views' 4 pairs each (8 slots)
__global__ __launch_bounds__(256) void combine_kernel(float* __restrict__ out)
{
    int idx = blockIdx.x * 256 + threadIdx.x;
    if (idx >= N_TOK * (DIM/4)) return;
    int t = idx >> 7, d = (idx & 127) << 2;
    float4 acc = make_float4(0.f, 0.f, 0.f, 0.f);
#pragma unroll
    for (int s = 0; s < TOPK; s++) {
        int p0 = g_pairpos[t*TOPK + s];
        int p1 = g_pairpos[(t + N_TOK)*TOPK + s];
        float4 v0 = *(const float4*)(g_slot + (size_t)p0 * DIM + d);
        float4 v1 = *(const float4*)(g_slot + (size_t)p1 * DIM + d);
        acc.x += v0.x + v1.x; acc.y += v0.y + v1.y;
        acc.z += v0.z + v1.z; acc.w += v0.w + v1.w;
    }
    *(float4*)(out + (size_t)t * DIM + d) = acc;
}

// ---------------- host -----------------------------------------------------
#define STG_OF(BM, BN, AL) ((AL) * (BM) * 80 + 32 * ((BN) * 2 + 16))

extern "C" void kernel_launch(void* const* d_in, const int* in_sizes, int n_in,
                              void* d_out, int out_size)
{
    const float* view[2]  = {(const float*)d_in[0], (const float*)d_in[1]};
    const float* proj_w   = (const float*)d_in[2];
    const float* proj_b   = (const float*)d_in[3];
    const float* router_w = (const float*)d_in[4];
    const float* keys     = (const float*)d_in[5];
    const float* w1       = (const float*)d_in[6];
    const float* b1       = (const float*)d_in[7];
    const float* w2       = (const float*)d_in[8];
    const float* b2       = (const float*)d_in[9];
    float* out = (float*)d_out;

    void *xhi,*xlo,*hhi,*hlo,*pw,*rw,*w1p,*w2p,*hid;
    cudaGetSymbolAddress(&xhi, g_x_hi);  cudaGetSymbolAddress(&xlo, g_x_lo);
    cudaGetSymbolAddress(&hhi, g_h_hi);  cudaGetSymbolAddress(&hlo, g_h_lo);
    cudaGetSymbolAddress(&pw, g_pw);     cudaGetSymbolAddress(&rw, g_rw);
    cudaGetSymbolAddress(&w1p, g_w1);    cudaGetSymbolAddress(&w2p, g_w2);
    cudaGetSymbolAddress(&hid, g_hid);

    constexpr int SM_PR = 3 * STG_OF(128, 256, 2);          // 112128
    constexpr int SM_F1 = 3 * STG_OF(256, 128, 1) + 1024;   // 88576
    constexpr int SM_F2 = 3 * STG_OF(128, 256, 1);          // 81408
    cudaFuncSetAttribute((const void*)mma_gemm_kernel<0,512,512,128,256,2>,
                         cudaFuncAttributeMaxDynamicSharedMemorySize, SM_PR);
    cudaFuncSetAttribute((const void*)mma_gemm_kernel<1,512,512,128,256,2>,
                         cudaFuncAttributeMaxDynamicSharedMemorySize, SM_PR);
    cudaFuncSetAttribute((const void*)mma_gemm_kernel<2,512,2048,256,128,1>,
                         cudaFuncAttributeMaxDynamicSharedMemorySize, SM_F1);
    cudaFuncSetAttribute((const void*)mma_gemm_kernel<3,2048,512,128,256,1>,
                         cudaFuncAttributeMaxDynamicSharedMemorySize, SM_F2);

    conv8_kernel<<<(2*DIM*DIM/8+255)/256, 256>>>(proj_w,   (__half*)pw,  2*DIM*DIM);
    conv8_kernel<<<(2*DIM*DIM/8+255)/256, 256>>>(router_w, (__half*)rw,  2*DIM*DIM);
    conv8_kernel<<<(N_EXP*DIM*HID/8+255)/256, 256>>>(w1,   (__half*)w1p, N_EXP*DIM*HID);
    conv8_kernel<<<(N_EXP*HID*DIM/8+255)/256, 256>>>(w2,   (__half*)w2p, N_EXP*HID*DIM);

    // both views into combined buffers
    split8_kernel<<<(N_TOK*DIM/8+255)/256, 256>>>(view[0],
        (__half*)xhi, (__half*)xlo, N_TOK*DIM);
    split8_kernel<<<(N_TOK*DIM/8+255)/256, 256>>>(view[1],
        (__half*)xhi + (size_t)N_TOK*DIM, (__half*)xlo + (size_t)N_TOK*DIM, N_TOK*DIM);

    dim3 gpr(DIM/256, N_TOKV/128);       // (2, 64)
    dim3 gf1(HID/128, MAX_T256);         // (16, 160)
    dim3 gf2(DIM/256, MAX_T128);         // (2, 320)

    mma_gemm_kernel<0,512,512,128,256,2><<<gpr, 256, SM_PR>>>(
        (const __half*)xhi, (const __half*)xlo, (const __half*)pw, proj_b);
    mma_gemm_kernel<1,512,512,128,256,2><<<gpr, 256, SM_PR>>>(
        (const __half*)hhi, (const __half*)hlo, (const __half*)rw, nullptr);
    reset_kernel<<<1, 32>>>();
    gate_kernel<<<N_TOKV/8, 256>>>(keys);
    scan_kernel<<<1, 1>>>();
    scatter_kernel<<<N_TOKV/128, 128>>>();
    mma_gemm_kernel<2,512,2048,256,128,1><<<gf1, 256, SM_F1>>>(
        (const __half*)hhi, nullptr, (const __half*)w1p, b1);
    mma_gemm_kernel<3,2048,512,128,256,1><<<gf2, 256, SM_F2>>>(
        (const __half*)hid, nullptr, (const __half*)w2p, b2);
    combine_kernel<<<(N_TOK*(DIM/4)+255)/256, 256>>>(out);
}

// round 12
// speedup vs baseline: 5.8631x; 1.1314x over previous
#include <cuda_runtime.h>
#include <cuda_fp16.h>
#include <math.h>
#include <stdint.h>

#define N_TOK    4096
#define N_TOKV   8192            // both views batched
#define DIM      512
#define N_EXP    16
#define TOPK     4
#define HID      2048
#define PAIR_CAP 36864           // 32768 pairs + 16 experts * 256 pad
#define MAX_T256 160
#define MAX_T128 320

// ---------------- device scratch -------------------------------------------
__device__ __half g_x_hi [N_TOKV * DIM];
__device__ __half g_x_lo [N_TOKV * DIM];
__device__ __half g_h_hi [N_TOKV * DIM];
__device__ __half g_h_lo [N_TOKV * DIM];
__device__ float  g_r    [N_TOKV * DIM];
__device__ __half g_pw [2 * DIM * DIM];
__device__ __half g_rw [2 * DIM * DIM];
__device__ __half g_w1 [N_EXP * DIM * HID];
__device__ __half g_w2 [N_EXP * HID * DIM];
__device__ __half g_hid [(size_t)PAIR_CAP * HID];
__device__ __half g_slot[(size_t)PAIR_CAP * DIM];

__device__ int   g_pair_token[PAIR_CAP];      // zero-init: pads read row 0 (harmless)
__device__ float g_pair_gate [PAIR_CAP];
__device__ int   g_pairpos [N_TOKV * TOPK];
__device__ int   g_tok_eidx[N_TOKV * TOPK];
__device__ float g_tok_gate[N_TOKV * TOPK];
__device__ int   g_counts [N_EXP];
__device__ int   g_offsets[N_EXP + 1];
__device__ int   g_cursor [N_EXP];
__device__ int   g_t256_e [MAX_T256];
__device__ int   g_t256_m0[MAX_T256];
__device__ int   g_t128_e [MAX_T128];
__device__ int   g_t128_m0[MAX_T128];
__device__ int   g_nt256, g_nt128;

// ---------------- asm helpers ----------------------------------------------
__device__ __forceinline__ uint32_t smem_u32(const void* p) {
    uint32_t a;
    asm("{ .reg .u64 t; cvta.to.shared.u64 t, %1; cvt.u32.u64 %0, t; }" : "=r"(a) : "l"(p));
    return a;
}
__device__ __forceinline__ void cpa16(uint32_t s, const void* g) {
    asm volatile("cp.async.cg.shared.global [%0], [%1], 16;" :: "r"(s), "l"(g));
}
#define CP_COMMIT() asm volatile("cp.async.commit_group;" ::: "memory")
#define CP_WAIT(n)  asm volatile("cp.async.wait_group %0;" :: "n"(n) : "memory")

__device__ __forceinline__ void ldm_x4(uint32_t* r, uint32_t a) {
    asm volatile("ldmatrix.sync.aligned.m8n8.x4.shared.b16 {%0,%1,%2,%3}, [%4];"
        : "=r"(r[0]), "=r"(r[1]), "=r"(r[2]), "=r"(r[3]) : "r"(a));
}
__device__ __forceinline__ void ldm_x4_t(uint32_t* r, uint32_t a) {
    asm volatile("ldmatrix.sync.aligned.m8n8.x4.trans.shared.b16 {%0,%1,%2,%3}, [%4];"
        : "=r"(r[0]), "=r"(r[1]), "=r"(r[2]), "=r"(r[3]) : "r"(a));
}
__device__ __forceinline__ void mma_fp16(float* d, const uint32_t* a, uint32_t b0, uint32_t b1) {
    asm volatile("mma.sync.aligned.m16n8k16.row.col.f32.f16.f16.f32 "
        "{%0,%1,%2,%3}, {%4,%5,%6,%7}, {%8,%9}, {%0,%1,%2,%3};"
        : "+f"(d[0]), "+f"(d[1]), "+f"(d[2]), "+f"(d[3])
        : "r"(a[0]), "r"(a[1]), "r"(a[2]), "r"(a[3]), "r"(b0), "r"(b1));
}
__device__ __forceinline__ float gelu_exact(float x) {
    return 0.5f * x * (1.0f + erff(x * 0.70710678118654752440f));
}

// ---------------- HMMA GEMM ------------------------------------------------
// A row-major fp16 (ALIMB limbs), B row-major fp16 [K][N] (ldmatrix.trans).
// 8 warps, 64x64 warp tiles, 4-stage cp.async pipeline, ONE barrier/chunk.
// MODE 0: proj  (z = view from m0; +bias -> g_h hi/lo)
// MODE 1: router(z = view from m0; -> g_r fp32)
// MODE 2: ffn1  (indirect A rows; +bias,gelu -> g_hid fp16)
// MODE 3: ffn2  (+bias,*gate -> g_slot fp16)
template<int MODE, int KLEN, int NTOT, int BM, int BN, int ALIMB>
__global__ __launch_bounds__(256, 1) void mma_gemm_kernel(
    const __half* __restrict__ Ah, const __half* __restrict__ Al,
    const __half* __restrict__ B,
    const float* __restrict__ bias)
{
    constexpr int NC   = KLEN / 32;
    constexpr int PB   = BN * 2 + 16;
    constexpr int ABY  = BM * 80;
    constexpr int BOFF = ALIMB * ABY;
    constexpr int STG  = ALIMB * ABY + 32 * PB;
    constexpr int WR   = BM / 64;

    int n0 = blockIdx.x * BN, m0, z;
    if (MODE <= 1) { m0 = blockIdx.y * BM; z = (m0 >= N_TOK) ? 1 : 0; }
    else if (MODE == 2) {
        if ((int)blockIdx.y >= g_nt256) return;
        z = g_t256_e[blockIdx.y]; m0 = g_t256_m0[blockIdx.y];
    } else {
        if ((int)blockIdx.y >= g_nt128) return;
        z = g_t128_e[blockIdx.y]; m0 = g_t128_m0[blockIdx.y];
    }
    const __half* Bz = B + (size_t)z * KLEN * NTOT;

    extern __shared__ __align__(16) char smem[];
    uint32_t sb = smem_u32(smem);

    const int tid = threadIdx.x, lane = tid & 31, warp = tid >> 5;
    const int mw = (warp % WR) * 64, nw = (warp / WR) * 64;
    const int lr = lane & 15, lc = (lane >> 4) << 3;

    int* tok = (int*)(smem + 4 * STG);
    if (MODE == 2) {
        if (tid < BM) tok[tid] = g_pair_token[m0 + tid];
        __syncthreads();
    }

    auto load_stage = [&](int s, int c) {
        const int k0 = c * 32;
        const uint32_t base = sb + (uint32_t)s * STG;
#pragma unroll
        for (int ch = tid; ch < BM * 4; ch += 256) {
            int row = ch >> 2, kc = ch & 3;
            const __half* src;
            if (MODE == 2) src = Ah + (size_t)tok[row] * KLEN + k0 + kc * 8;
            else           src = Ah + (size_t)(m0 + row) * KLEN + k0 + kc * 8;
            cpa16(base + row * 80 + kc * 16, src);
            if (ALIMB == 2)
                cpa16(base + ABY + row * 80 + kc * 16,
                      Al + (size_t)(m0 + row) * KLEN + k0 + kc * 8);
        }
#pragma unroll
        for (int ch = tid; ch < BN * 4; ch += 256) {
            int row = ch / (BN / 8), nc = ch % (BN / 8);
            cpa16(base + BOFF + row * PB + nc * 16,
                  Bz + (size_t)(k0 + row) * NTOT + n0 + nc * 8);
        }
    };

    float acc[4][8][4];
#pragma unroll
    for (int a = 0; a < 4; a++)
#pragma unroll
        for (int b = 0; b < 8; b++)
#pragma unroll
            for (int d = 0; d < 4; d++) acc[a][b][d] = 0.f;

    load_stage(0, 0); CP_COMMIT();
    if (NC > 1) { load_stage(1, 1); CP_COMMIT(); }

    for (int c = 0; c < NC; c++) {
        if (c + 2 < NC) { load_stage((c + 2) & 3, c + 2); CP_COMMIT(); CP_WAIT(2); }
        else if (c + 1 < NC) CP_WAIT(1);
        else CP_WAIT(0);
        __syncthreads();          // single barrier: 4 stages / distance-2 prefetch

        const uint32_t base = sb + (uint32_t)(c & 3) * STG;
#pragma unroll
        for (int ks = 0; ks < 2; ks++) {
            uint32_t a1[4][4], a2[4][4];
#pragma unroll
            for (int ms = 0; ms < 4; ms++) {
                uint32_t ad = base + (uint32_t)((mw + ms * 16 + lr) * 80 + (ks * 16 + lc) * 2);
                ldm_x4(a1[ms], ad);
                if (ALIMB == 2) ldm_x4(a2[ms], ad + ABY);
            }
#pragma unroll
            for (int np = 0; np < 4; np++) {
                uint32_t bf[4];
                uint32_t bd = base + BOFF + (uint32_t)((ks * 16 + lr) * PB + (nw + np * 16 + lc) * 2);
                ldm_x4_t(bf, bd);
#pragma unroll
                for (int ms = 0; ms < 4; ms++)
#pragma unroll
                    for (int sub = 0; sub < 2; sub++) {
                        int ns = np * 2 + sub;
                        mma_fp16(acc[ms][ns], a1[ms], bf[sub*2], bf[sub*2+1]);
                        if (ALIMB == 2)
                            mma_fp16(acc[ms][ns], a2[ms], bf[sub*2], bf[sub*2+1]);
                    }
            }
        }
    }

    // ---- epilogue ----
    const int lrow = lane >> 2, lcol = (lane & 3) * 2;
#pragma unroll
    for (int ms = 0; ms < 4; ms++) {
        int r0 = m0 + mw + ms * 16 + lrow;
        float gt0 = 0.f, gt1 = 0.f;
        if (MODE == 3) { gt0 = g_pair_gate[r0]; gt1 = g_pair_gate[r0 + 8]; }
#pragma unroll
        for (int ns = 0; ns < 8; ns++) {
            int cc = n0 + nw + ns * 8 + lcol;
            float b0 = 0.f, b1 = 0.f;
            if (MODE != 1) {
                b0 = bias[(size_t)z * NTOT + cc];
                b1 = bias[(size_t)z * NTOT + cc + 1];
            }
            float v00 = acc[ms][ns][0] + b0, v01 = acc[ms][ns][1] + b1;
            float v10 = acc[ms][ns][2] + b0, v11 = acc[ms][ns][3] + b1;
            if (MODE == 2) {
                v00 = gelu_exact(v00); v01 = gelu_exact(v01);
                v10 = gelu_exact(v10); v11 = gelu_exact(v11);
            }
            if (MODE == 3) { v00 *= gt0; v01 *= gt0; v10 *= gt1; v11 *= gt1; }
            if (MODE == 1) {
                *(float2*)(g_r + (size_t)r0 * NTOT + cc)       = make_float2(v00, v01);
                *(float2*)(g_r + (size_t)(r0 + 8) * NTOT + cc) = make_float2(v10, v11);
            } else if (MODE == 2 || MODE == 3) {
                __half* OUT = (MODE == 2) ? g_hid : g_slot;
                *(__half2*)(OUT + (size_t)r0 * NTOT + cc) =
                    __halves2half2(__float2half(v00), __float2half(v01));
                *(__half2*)(OUT + (size_t)(r0 + 8) * NTOT + cc) =
                    __halves2half2(__float2half(v10), __float2half(v11));
            } else {
                __half h00 = __float2half(v00), h01 = __float2half(v01);
                __half h10 = __float2half(v10), h11 = __float2half(v11);
                *(__half2*)(g_h_hi + (size_t)r0 * NTOT + cc)       = __halves2half2(h00, h01);
                *(__half2*)(g_h_hi + (size_t)(r0 + 8) * NTOT + cc) = __halves2half2(h10, h11);
                *(__half2*)(g_h_lo + (size_t)r0 * NTOT + cc) =
                    __halves2half2(__float2half(v00 - __half2float(h00)),
                                   __float2half(v01 - __half2float(h01)));
                *(__half2*)(g_h_lo + (size_t)(r0 + 8) * NTOT + cc) =
                    __halves2half2(__float2half(v10 - __half2float(h10)),
                                   __float2half(v11 - __half2float(h11)));
            }
        }
    }
}

// ---------------- small kernels ---------------------------------------------
__global__ __launch_bounds__(256) void split8_kernel(
    const float* __restrict__ in, __half* __restrict__ hi,
    __half* __restrict__ lo, int n)
{
    int i = (blockIdx.x * 256 + threadIdx.x) * 8;
    if (i >= n) return;
    float4 a = *(const float4*)(in + i);
    float4 b = *(const float4*)(in + i + 4);
    float v[8] = {a.x, a.y, a.z, a.w, b.x, b.y, b.z, b.w};
    union { __half2 p[4]; uint4 u; } ph, pl;
#pragma unroll
    for (int j = 0; j < 4; j++) {
        __half h0 = __float2half(v[2*j]);
        __half h1 = __float2half(v[2*j+1]);
        ph.p[j] = __halves2half2(h0, h1);
        pl.p[j] = __halves2half2(
            __float2half(v[2*j]   - __half2float(h0)),
            __float2half(v[2*j+1] - __half2float(h1)));
    }
    *(uint4*)(hi + i) = ph.u;
    *(uint4*)(lo + i) = pl.u;
}

__global__ __launch_bounds__(256) void conv8_kernel(
    const float* __restrict__ in, __half* __restrict__ out, int n)
{
    int i = (blockIdx.x * 256 + threadIdx.x) * 8;
    if (i >= n) return;
    float4 a = *(const float4*)(in + i);
    float4 b = *(const float4*)(in + i + 4);
    float v[8] = {a.x, a.y, a.z, a.w, b.x, b.y, b.z, b.w};
    union { __half2 p[4]; uint4 u; } ph;
#pragma unroll
    for (int j = 0; j < 4; j++)
        ph.p[j] = __halves2half2(__float2half(v[2*j]), __float2half(v[2*j+1]));
    *(uint4*)(out + i) = ph.u;
}

// warp-per-token gate: 8 tokens/block, keys staged in smem
__global__ __launch_bounds__(256) void gate_kernel(const float* __restrict__ keys)
{
    __shared__ float ks[N_EXP][DIM];
    const int tid = threadIdx.x;
    for (int i = tid; i < N_EXP * DIM; i += 256)
        ks[i >> 9][i & 511] = keys[i];
    __syncthreads();

    const int warp = tid >> 5, lane = tid & 31;
    const int t = blockIdx.x * 8 + warp;
    const float* rr = g_r + (size_t)t * DIM;
    float rv[16];
#pragma unroll
    for (int j = 0; j < 16; j++) rv[j] = rr[lane + 32 * j];

    float lg[N_EXP];
#pragma unroll
    for (int e = 0; e < N_EXP; e++) {
        float s = 0.f;
#pragma unroll
        for (int j = 0; j < 16; j++) {
            float d = rv[j] - ks[e][lane + 32 * j];
            s = fmaf(d, d, s);
        }
#pragma unroll
        for (int o = 16; o > 0; o >>= 1)
            s += __shfl_xor_sync(0xFFFFFFFF, s, o);
        lg[e] = -sqrtf(fmaxf(s, 0.f));
    }
    if (lane == 0) {
        int idx[TOPK]; float val[TOPK]; bool used[N_EXP];
#pragma unroll
        for (int i = 0; i < N_EXP; i++) used[i] = false;
        for (int s2 = 0; s2 < TOPK; s2++) {
            int bi = -1; float bv = -1e30f;
            for (int i = 0; i < N_EXP; i++)
                if (!used[i] && lg[i] > bv) { bv = lg[i]; bi = i; }
            used[bi] = true; idx[s2] = bi; val[s2] = bv;
        }
        float mx = val[0], ex[TOPK], se = 0.f;
        for (int s2 = 0; s2 < TOPK; s2++) { ex[s2] = expf(val[s2] - mx); se += ex[s2]; }
        float inv = 1.0f / se;
        for (int s2 = 0; s2 < TOPK; s2++) {
            g_tok_eidx[t*TOPK + s2] = idx[s2];
            g_tok_gate[t*TOPK + s2] = ex[s2] * inv;
            atomicAdd(&g_counts[idx[s2]], 1);
        }
    }
}

__global__ void reset_kernel() {
    if (threadIdx.x < N_EXP) g_counts[threadIdx.x] = 0;
}

__global__ void scan_kernel() {
    if (threadIdx.x == 0) {
        int o = 0, n256 = 0, n128 = 0;
        for (int e = 0; e < N_EXP; e++) {
            g_offsets[e] = o; g_cursor[e] = o;
            int seg = ((g_counts[e] + 255) >> 8) << 8;
            for (int i = 0; i < seg / 256; i++) { g_t256_e[n256] = e; g_t256_m0[n256] = o + i * 256; n256++; }
            for (int i = 0; i < seg / 128; i++) { g_t128_e[n128] = e; g_t128_m0[n128] = o + i * 128; n128++; }
            o += seg;
        }
        g_offsets[N_EXP] = o;
        g_nt256 = n256; g_nt128 = n128;
    }
}

__global__ __launch_bounds__(128) void scatter_kernel() {
    int t = blockIdx.x * 128 + threadIdx.x;
    if (t >= N_TOKV) return;
    for (int s = 0; s < TOPK; s++) {
        int e = g_tok_eidx[t*TOPK + s];
        int p = atomicAdd(&g_cursor[e], 1);
        g_pair_token[p] = t;
        g_pair_gate[p]  = g_tok_gate[t*TOPK + s];
        g_pairpos[t*TOPK + s] = p;
    }
}

// out[t] = sum over both views' 4 pairs each (8 slots, fp16 slot buffer)
__global__ __launch_bounds__(256) void combine_kernel(float* __restrict__ out)
{
    int idx = blockIdx.x * 256 + threadIdx.x;
    if (idx >= N_TOK * (DIM/4)) return;
    int t = idx >> 7, d = (idx & 127) << 2;
    float acc0 = 0.f, acc1 = 0.f, acc2 = 0.f, acc3 = 0.f;
#pragma unroll
    for (int s = 0; s < TOPK; s++) {
        int p0 = g_pairpos[t*TOPK + s];
        int p1 = g_pairpos[(t + N_TOK)*TOPK + s];
        uint2 u0 = *(const uint2*)(g_slot + (size_t)p0 * DIM + d);
        uint2 u1 = *(const uint2*)(g_slot + (size_t)p1 * DIM + d);
        float2 a0 = __half22float2(*(__half2*)&u0.x);
        float2 a1 = __half22float2(*(__half2*)&u0.y);
        float2 b0 = __half22float2(*(__half2*)&u1.x);
        float2 b1 = __half22float2(*(__half2*)&u1.y);
        acc0 += a0.x + b0.x; acc1 += a0.y + b0.y;
        acc2 += a1.x + b1.x; acc3 += a1.y + b1.y;
    }
    *(float4*)(out + (size_t)t * DIM + d) = make_float4(acc0, acc1, acc2, acc3);
}

// ---------------- host -----------------------------------------------------
#define STG_OF(BM, BN, AL) ((AL) * (BM) * 80 + 32 * ((BN) * 2 + 16))

extern "C" void kernel_launch(void* const* d_in, const int* in_sizes, int n_in,
                              void* d_out, int out_size)
{
    const float* view[2]  = {(const float*)d_in[0], (const float*)d_in[1]};
    const float* proj_w   = (const float*)d_in[2];
    const float* proj_b   = (const float*)d_in[3];
    const float* router_w = (const float*)d_in[4];
    const float* keys     = (const float*)d_in[5];
    const float* w1       = (const float*)d_in[6];
    const float* b1       = (const float*)d_in[7];
    const float* w2       = (const float*)d_in[8];
    const float* b2       = (const float*)d_in[9];
    float* out = (float*)d_out;

    void *xhi,*xlo,*hhi,*hlo,*pw,*rw,*w1p,*w2p,*hid;
    cudaGetSymbolAddress(&xhi, g_x_hi);  cudaGetSymbolAddress(&xlo, g_x_lo);
    cudaGetSymbolAddress(&hhi, g_h_hi);  cudaGetSymbolAddress(&hlo, g_h_lo);
    cudaGetSymbolAddress(&pw, g_pw);     cudaGetSymbolAddress(&rw, g_rw);
    cudaGetSymbolAddress(&w1p, g_w1);    cudaGetSymbolAddress(&w2p, g_w2);
    cudaGetSymbolAddress(&hid, g_hid);

    constexpr int SM_PR = 4 * STG_OF(128, 256, 2);          // 149504
    constexpr int SM_F1 = 4 * STG_OF(256, 128, 1) + 1024;   // 117760
    constexpr int SM_F2 = 4 * STG_OF(128, 256, 1);          // 108544
    cudaFuncSetAttribute((const void*)mma_gemm_kernel<0,512,512,128,256,2>,
                         cudaFuncAttributeMaxDynamicSharedMemorySize, SM_PR);
    cudaFuncSetAttribute((const void*)mma_gemm_kernel<1,512,512,128,256,2>,
                         cudaFuncAttributeMaxDynamicSharedMemorySize, SM_PR);
    cudaFuncSetAttribute((const void*)mma_gemm_kernel<2,512,2048,256,128,1>,
                         cudaFuncAttributeMaxDynamicSharedMemorySize, SM_F1);
    cudaFuncSetAttribute((const void*)mma_gemm_kernel<3,2048,512,128,256,1>,
                         cudaFuncAttributeMaxDynamicSharedMemorySize, SM_F2);

    conv8_kernel<<<(2*DIM*DIM/8+255)/256, 256>>>(proj_w,   (__half*)pw,  2*DIM*DIM);
    conv8_kernel<<<(2*DIM*DIM/8+255)/256, 256>>>(router_w, (__half*)rw,  2*DIM*DIM);
    conv8_kernel<<<(N_EXP*DIM*HID/8+255)/256, 256>>>(w1,   (__half*)w1p, N_EXP*DIM*HID);
    conv8_kernel<<<(N_EXP*HID*DIM/8+255)/256, 256>>>(w2,   (__half*)w2p, N_EXP*HID*DIM);

    split8_kernel<<<(N_TOK*DIM/8+255)/256, 256>>>(view[0],
        (__half*)xhi, (__half*)xlo, N_TOK*DIM);
    split8_kernel<<<(N_TOK*DIM/8+255)/256, 256>>>(view[1],
        (__half*)xhi + (size_t)N_TOK*DIM, (__half*)xlo + (size_t)N_TOK*DIM, N_TOK*DIM);

    dim3 gpr(DIM/256, N_TOKV/128);       // (2, 64)
    dim3 gf1(HID/128, MAX_T256);         // (16, 160)
    dim3 gf2(DIM/256, MAX_T128);         // (2, 320)

    mma_gemm_kernel<0,512,512,128,256,2><<<gpr, 256, SM_PR>>>(
        (const __half*)xhi, (const __half*)xlo, (const __half*)pw, proj_b);
    mma_gemm_kernel<1,512,512,128,256,2><<<gpr, 256, SM_PR>>>(
        (const __half*)hhi, (const __half*)hlo, (const __half*)rw, nullptr);
    reset_kernel<<<1, 32>>>();
    gate_kernel<<<N_TOKV/8, 256>>>(keys);
    scan_kernel<<<1, 1>>>();
    scatter_kernel<<<N_TOKV/128, 128>>>();
    mma_gemm_kernel<2,512,2048,256,128,1><<<gf1, 256, SM_F1>>>(
        (const __half*)hhi, nullptr, (const __half*)w1p, b1);
    mma_gemm_kernel<3,2048,512,128,256,1><<<gf2, 256, SM_F2>>>(
        (const __half*)hid, nullptr, (const __half*)w2p, b2);
    combine_kernel<<<(N_TOK*(DIM/4)+255)/256, 256>>>(out);
}

// round 13
// speedup vs baseline: 6.7159x; 1.1455x over previous
#include <cuda_runtime.h>
#include <cuda_fp16.h>
#include <math.h>
#include <stdint.h>

#define N_TOK    4096
#define N_TOKV   8192            // both views batched
#define DIM      512
#define N_EXP    16
#define TOPK     4
#define HID      2048
#define PAIR_CAP 36864           // 32768 pairs + 16 experts * 128 pad (34800 max)
#define MAX_TILES 272            // 32768/128 + 16

// ---------------- device scratch -------------------------------------------
__device__ __half g_x_hi [N_TOKV * DIM];
__device__ __half g_x_lo [N_TOKV * DIM];
__device__ __half g_h_hi [N_TOKV * DIM];
__device__ __half g_h_lo [N_TOKV * DIM];
__device__ float  g_r    [N_TOKV * DIM];
__device__ __half g_pw [2 * DIM * DIM];
__device__ __half g_rw [2 * DIM * DIM];
__device__ __half g_w1 [N_EXP * DIM * HID];
__device__ __half g_w2 [N_EXP * HID * DIM];
__device__ __half g_hid [(size_t)PAIR_CAP * HID];
__device__ __half g_slot[(size_t)PAIR_CAP * DIM];

__device__ int   g_pair_token[PAIR_CAP];      // zero-init: pads read row 0 (harmless)
__device__ float g_pair_gate [PAIR_CAP];
__device__ int   g_pairpos [N_TOKV * TOPK];
__device__ int   g_tok_eidx[N_TOKV * TOPK];
__device__ float g_tok_gate[N_TOKV * TOPK];
__device__ int   g_counts [N_EXP];
__device__ int   g_offsets[N_EXP + 1];
__device__ int   g_cursor [N_EXP];
__device__ int   g_tile_e [MAX_TILES];
__device__ int   g_tile_m0[MAX_TILES];
__device__ int   g_ntiles;

// ---------------- asm helpers ----------------------------------------------
__device__ __forceinline__ uint32_t smem_u32(const void* p) {
    uint32_t a;
    asm("{ .reg .u64 t; cvta.to.shared.u64 t, %1; cvt.u32.u64 %0, t; }" : "=r"(a) : "l"(p));
    return a;
}
__device__ __forceinline__ void cpa16(uint32_t s, const void* g) {
    asm volatile("cp.async.cg.shared.global [%0], [%1], 16;" :: "r"(s), "l"(g));
}
#define CP_COMMIT() asm volatile("cp.async.commit_group;" ::: "memory")
#define CP_WAIT(n)  asm volatile("cp.async.wait_group %0;" :: "n"(n) : "memory")

__device__ __forceinline__ void ldm_x4(uint32_t* r, uint32_t a) {
    asm volatile("ldmatrix.sync.aligned.m8n8.x4.shared.b16 {%0,%1,%2,%3}, [%4];"
        : "=r"(r[0]), "=r"(r[1]), "=r"(r[2]), "=r"(r[3]) : "r"(a));
}
__device__ __forceinline__ void ldm_x4_t(uint32_t* r, uint32_t a) {
    asm volatile("ldmatrix.sync.aligned.m8n8.x4.trans.shared.b16 {%0,%1,%2,%3}, [%4];"
        : "=r"(r[0]), "=r"(r[1]), "=r"(r[2]), "=r"(r[3]) : "r"(a));
}
__device__ __forceinline__ void mma_fp16(float* d, const uint32_t* a, uint32_t b0, uint32_t b1) {
    asm volatile("mma.sync.aligned.m16n8k16.row.col.f32.f16.f16.f32 "
        "{%0,%1,%2,%3}, {%4,%5,%6,%7}, {%8,%9}, {%0,%1,%2,%3};"
        : "+f"(d[0]), "+f"(d[1]), "+f"(d[2]), "+f"(d[3])
        : "r"(a[0]), "r"(a[1]), "r"(a[2]), "r"(a[3]), "r"(b0), "r"(b1));
}
__device__ __forceinline__ float gelu_exact(float x) {
    return 0.5f * x * (1.0f + erff(x * 0.70710678118654752440f));
}

// ---------------- HMMA GEMM ------------------------------------------------
// A row-major fp16 (ALIMB limbs), B row-major fp16 [K][N] (ldmatrix.trans).
// 8 warps, 64x64 warp tiles, 4-stage cp.async pipeline, ONE barrier/chunk,
// prefetch distance 2 (race-free: writes target 2-generation-old buffers).
// MODE 0: proj  (z = view from m0; +bias -> g_h hi/lo)
// MODE 1: router(z = view from m0; -> g_r fp32)
// MODE 2: ffn1  (indirect A rows; +bias,gelu -> g_hid fp16)
// MODE 3: ffn2  (+bias,*gate -> g_slot fp16)
template<int MODE, int KLEN, int NTOT, int BM, int BN, int ALIMB, int BK>
__global__ __launch_bounds__(256, 1) void mma_gemm_kernel(
    const __half* __restrict__ Ah, const __half* __restrict__ Al,
    const __half* __restrict__ B,
    const float* __restrict__ bias)
{
    constexpr int NC   = KLEN / BK;
    constexpr int KS   = BK / 16;
    constexpr int PA   = BK * 2 + 16;
    constexpr int PB   = BN * 2 + 16;
    constexpr int ABY  = BM * PA;
    constexpr int BOFF = ALIMB * ABY;
    constexpr int STG  = ALIMB * ABY + BK * PB;
    constexpr int WR   = BM / 64;
    constexpr int ARC  = BK / 8;            // A 16B-chunks per row
    constexpr int BRC  = BN / 8;            // B 16B-chunks per row
    constexpr int ACH  = BM * ARC;
    constexpr int BCH  = BK * BRC;

    int n0 = blockIdx.x * BN, m0, z;
    if (MODE <= 1) { m0 = blockIdx.y * BM; z = (m0 >= N_TOK) ? 1 : 0; }
    else {
        if ((int)blockIdx.y >= g_ntiles) return;
        z = g_tile_e[blockIdx.y]; m0 = g_tile_m0[blockIdx.y];
    }
    const __half* Bz = B + (size_t)z * KLEN * NTOT;

    extern __shared__ __align__(16) char smem[];
    uint32_t sb = smem_u32(smem);

    const int tid = threadIdx.x, lane = tid & 31, warp = tid >> 5;
    const int mw = (warp % WR) * 64, nw = (warp / WR) * 64;
    const int lr = lane & 15, lc = (lane >> 4) << 3;

    int* tok = (int*)(smem + 4 * STG);
    if (MODE == 2) {
        if (tid < BM) tok[tid] = g_pair_token[m0 + tid];
        __syncthreads();
    }

    auto load_stage = [&](int s, int c) {
        const int k0 = c * BK;
        const uint32_t base = sb + (uint32_t)s * STG;
#pragma unroll
        for (int ch = tid; ch < ACH; ch += 256) {
            int row = ch / ARC, kc = ch % ARC;
            const __half* src;
            if (MODE == 2) src = Ah + (size_t)tok[row] * KLEN + k0 + kc * 8;
            else           src = Ah + (size_t)(m0 + row) * KLEN + k0 + kc * 8;
            cpa16(base + row * PA + kc * 16, src);
            if (ALIMB == 2)
                cpa16(base + ABY + row * PA + kc * 16,
                      Al + (size_t)(m0 + row) * KLEN + k0 + kc * 8);
        }
#pragma unroll
        for (int ch = tid; ch < BCH; ch += 256) {
            int row = ch / BRC, nc = ch % BRC;
            cpa16(base + BOFF + row * PB + nc * 16,
                  Bz + (size_t)(k0 + row) * NTOT + n0 + nc * 8);
        }
    };

    float acc[4][8][4];
#pragma unroll
    for (int a = 0; a < 4; a++)
#pragma unroll
        for (int b = 0; b < 8; b++)
#pragma unroll
            for (int d = 0; d < 4; d++) acc[a][b][d] = 0.f;

    load_stage(0, 0); CP_COMMIT();
    if (NC > 1) { load_stage(1, 1); CP_COMMIT(); }

    for (int c = 0; c < NC; c++) {
        if (c + 2 < NC) { load_stage((c + 2) & 3, c + 2); CP_COMMIT(); CP_WAIT(2); }
        else if (c + 1 < NC) CP_WAIT(1);
        else CP_WAIT(0);
        __syncthreads();          // single barrier: 4 stages / distance-2 prefetch

        const uint32_t base = sb + (uint32_t)(c & 3) * STG;
#pragma unroll
        for (int ks = 0; ks < KS; ks++) {
            uint32_t a1[4][4], a2[4][4];
#pragma unroll
            for (int ms = 0; ms < 4; ms++) {
                uint32_t ad = base + (uint32_t)((mw + ms * 16 + lr) * PA + (ks * 16 + lc) * 2);
                ldm_x4(a1[ms], ad);
                if (ALIMB == 2) ldm_x4(a2[ms], ad + ABY);
            }
#pragma unroll
            for (int np = 0; np < 4; np++) {
                uint32_t bf[4];
                uint32_t bd = base + BOFF + (uint32_t)((ks * 16 + lr) * PB + (nw + np * 16 + lc) * 2);
                ldm_x4_t(bf, bd);
#pragma unroll
                for (int ms = 0; ms < 4; ms++)
#pragma unroll
                    for (int sub = 0; sub < 2; sub++) {
                        int ns = np * 2 + sub;
                        mma_fp16(acc[ms][ns], a1[ms], bf[sub*2], bf[sub*2+1]);
                        if (ALIMB == 2)
                            mma_fp16(acc[ms][ns], a2[ms], bf[sub*2], bf[sub*2+1]);
                    }
            }
        }
    }

    // ---- epilogue ----
    const int lrow = lane >> 2, lcol = (lane & 3) * 2;
#pragma unroll
    for (int ms = 0; ms < 4; ms++) {
        int r0 = m0 + mw + ms * 16 + lrow;
        float gt0 = 0.f, gt1 = 0.f;
        if (MODE == 3) { gt0 = g_pair_gate[r0]; gt1 = g_pair_gate[r0 + 8]; }
#pragma unroll
        for (int ns = 0; ns < 8; ns++) {
            int cc = n0 + nw + ns * 8 + lcol;
            float b0 = 0.f, b1 = 0.f;
            if (MODE != 1) {
                b0 = bias[(size_t)z * NTOT + cc];
                b1 = bias[(size_t)z * NTOT + cc + 1];
            }
            float v00 = acc[ms][ns][0] + b0, v01 = acc[ms][ns][1] + b1;
            float v10 = acc[ms][ns][2] + b0, v11 = acc[ms][ns][3] + b1;
            if (MODE == 2) {
                v00 = gelu_exact(v00); v01 = gelu_exact(v01);
                v10 = gelu_exact(v10); v11 = gelu_exact(v11);
            }
            if (MODE == 3) { v00 *= gt0; v01 *= gt0; v10 *= gt1; v11 *= gt1; }
            if (MODE == 1) {
                *(float2*)(g_r + (size_t)r0 * NTOT + cc)       = make_float2(v00, v01);
                *(float2*)(g_r + (size_t)(r0 + 8) * NTOT + cc) = make_float2(v10, v11);
            } else if (MODE == 2 || MODE == 3) {
                __half* OUT = (MODE == 2) ? g_hid : g_slot;
                *(__half2*)(OUT + (size_t)r0 * NTOT + cc) =
                    __halves2half2(__float2half(v00), __float2half(v01));
                *(__half2*)(OUT + (size_t)(r0 + 8) * NTOT + cc) =
                    __halves2half2(__float2half(v10), __float2half(v11));
            } else {
                __half h00 = __float2half(v00), h01 = __float2half(v01);
                __half h10 = __float2half(v10), h11 = __float2half(v11);
                *(__half2*)(g_h_hi + (size_t)r0 * NTOT + cc)       = __halves2half2(h00, h01);
                *(__half2*)(g_h_hi + (size_t)(r0 + 8) * NTOT + cc) = __halves2half2(h10, h11);
                *(__half2*)(g_h_lo + (size_t)r0 * NTOT + cc) =
                    __halves2half2(__float2half(v00 - __half2float(h00)),
                                   __float2half(v01 - __half2float(h01)));
                *(__half2*)(g_h_lo + (size_t)(r0 + 8) * NTOT + cc) =
                    __halves2half2(__float2half(v10 - __half2float(h10)),
                                   __float2half(v11 - __half2float(h11)));
            }
        }
    }
}

// ---------------- small kernels ---------------------------------------------
__global__ __launch_bounds__(256) void split8_kernel(
    const float* __restrict__ in, __half* __restrict__ hi,
    __half* __restrict__ lo, int n)
{
    int i = (blockIdx.x * 256 + threadIdx.x) * 8;
    if (i >= n) return;
    float4 a = *(const float4*)(in + i);
    float4 b = *(const float4*)(in + i + 4);
    float v[8] = {a.x, a.y, a.z, a.w, b.x, b.y, b.z, b.w};
    union { __half2 p[4]; uint4 u; } ph, pl;
#pragma unroll
    for (int j = 0; j < 4; j++) {
        __half h0 = __float2half(v[2*j]);
        __half h1 = __float2half(v[2*j+1]);
        ph.p[j] = __halves2half2(h0, h1);
        pl.p[j] = __halves2half2(
            __float2half(v[2*j]   - __half2float(h0)),
            __float2half(v[2*j+1] - __half2float(h1)));
    }
    *(uint4*)(hi + i) = ph.u;
    *(uint4*)(lo + i) = pl.u;
}

__global__ __launch_bounds__(256) void conv8_kernel(
    const float* __restrict__ in, __half* __restrict__ out, int n)
{
    int i = (blockIdx.x * 256 + threadIdx.x) * 8;
    if (i >= n) return;
    float4 a = *(const float4*)(in + i);
    float4 b = *(const float4*)(in + i + 4);
    float v[8] = {a.x, a.y, a.z, a.w, b.x, b.y, b.z, b.w};
    union { __half2 p[4]; uint4 u; } ph;
#pragma unroll
    for (int j = 0; j < 4; j++)
        ph.p[j] = __halves2half2(__float2half(v[2*j]), __float2half(v[2*j+1]));
    *(uint4*)(out + i) = ph.u;
}

// warp-per-token gate: 8 tokens/block, keys staged in smem
__global__ __launch_bounds__(256) void gate_kernel(const float* __restrict__ keys)
{
    __shared__ float ks[N_EXP][DIM];
    const int tid = threadIdx.x;
    for (int i = tid; i < N_EXP * DIM; i += 256)
        ks[i >> 9][i & 511] = keys[i];
    __syncthreads();

    const int warp = tid >> 5, lane = tid & 31;
    const int t = blockIdx.x * 8 + warp;
    const float* rr = g_r + (size_t)t * DIM;
    float rv[16];
#pragma unroll
    for (int j = 0; j < 16; j++) rv[j] = rr[lane + 32 * j];

    float lg[N_EXP];
#pragma unroll
    for (int e = 0; e < N_EXP; e++) {
        float s = 0.f;
#pragma unroll
        for (int j = 0; j < 16; j++) {
            float d = rv[j] - ks[e][lane + 32 * j];
            s = fmaf(d, d, s);
        }
#pragma unroll
        for (int o = 16; o > 0; o >>= 1)
            s += __shfl_xor_sync(0xFFFFFFFF, s, o);
        lg[e] = -sqrtf(fmaxf(s, 0.f));
    }
    if (lane == 0) {
        int idx[TOPK]; float val[TOPK]; bool used[N_EXP];
#pragma unroll
        for (int i = 0; i < N_EXP; i++) used[i] = false;
        for (int s2 = 0; s2 < TOPK; s2++) {
            int bi = -1; float bv = -1e30f;
            for (int i = 0; i < N_EXP; i++)
                if (!used[i] && lg[i] > bv) { bv = lg[i]; bi = i; }
            used[bi] = true; idx[s2] = bi; val[s2] = bv;
        }
        float mx = val[0], ex[TOPK], se = 0.f;
        for (int s2 = 0; s2 < TOPK; s2++) { ex[s2] = expf(val[s2] - mx); se += ex[s2]; }
        float inv = 1.0f / se;
        for (int s2 = 0; s2 < TOPK; s2++) {
            g_tok_eidx[t*TOPK + s2] = idx[s2];
            g_tok_gate[t*TOPK + s2] = ex[s2] * inv;
            atomicAdd(&g_counts[idx[s2]], 1);
        }
    }
}

__global__ void reset_kernel() {
    if (threadIdx.x < N_EXP) g_counts[threadIdx.x] = 0;
}

__global__ void scan_kernel() {
    if (threadIdx.x == 0) {
        int o = 0, nt = 0;
        for (int e = 0; e < N_EXP; e++) {
            g_offsets[e] = o; g_cursor[e] = o;
            int seg = ((g_counts[e] + 127) >> 7) << 7;       // 128-aligned
            for (int i = 0; i < seg / 128; i++) { g_tile_e[nt] = e; g_tile_m0[nt] = o + (i << 7); nt++; }
            o += seg;
        }
        g_offsets[N_EXP] = o;
        g_ntiles = nt;
    }
}

__global__ __launch_bounds__(128) void scatter_kernel() {
    int t = blockIdx.x * 128 + threadIdx.x;
    if (t >= N_TOKV) return;
    for (int s = 0; s < TOPK; s++) {
        int e = g_tok_eidx[t*TOPK + s];
        int p = atomicAdd(&g_cursor[e], 1);
        g_pair_token[p] = t;
        g_pair_gate[p]  = g_tok_gate[t*TOPK + s];
        g_pairpos[t*TOPK + s] = p;
    }
}

// out[t] = sum over both views' 4 pairs each (8 slots, fp16 slot buffer)
__global__ __launch_bounds__(256) void combine_kernel(float* __restrict__ out)
{
    int idx = blockIdx.x * 256 + threadIdx.x;
    if (idx >= N_TOK * (DIM/4)) return;
    int t = idx >> 7, d = (idx & 127) << 2;
    float acc0 = 0.f, acc1 = 0.f, acc2 = 0.f, acc3 = 0.f;
#pragma unroll
    for (int s = 0; s < TOPK; s++) {
        int p0 = g_pairpos[t*TOPK + s];
        int p1 = g_pairpos[(t + N_TOK)*TOPK + s];
        uint2 u0 = *(const uint2*)(g_slot + (size_t)p0 * DIM + d);
        uint2 u1 = *(const uint2*)(g_slot + (size_t)p1 * DIM + d);
        float2 a0 = __half22float2(*(__half2*)&u0.x);
        float2 a1 = __half22float2(*(__half2*)&u0.y);
        float2 b0 = __half22float2(*(__half2*)&u1.x);
        float2 b1 = __half22float2(*(__half2*)&u1.y);
        acc0 += a0.x + b0.x; acc1 += a0.y + b0.y;
        acc2 += a1.x + b1.x; acc3 += a1.y + b1.y;
    }
    *(float4*)(out + (size_t)t * DIM + d) = make_float4(acc0, acc1, acc2, acc3);
}

// ---------------- host -----------------------------------------------------
#define STG_OF(BM, BN, AL, BK) ((AL) * (BM) * ((BK)*2+16) + (BK) * ((BN)*2+16))

extern "C" void kernel_launch(void* const* d_in, const int* in_sizes, int n_in,
                              void* d_out, int out_size)
{
    const float* view[2]  = {(const float*)d_in[0], (const float*)d_in[1]};
    const float* proj_w   = (const float*)d_in[2];
    const float* proj_b   = (const float*)d_in[3];
    const float* router_w = (const float*)d_in[4];
    const float* keys     = (const float*)d_in[5];
    const float* w1       = (const float*)d_in[6];
    const float* b1       = (const float*)d_in[7];
    const float* w2       = (const float*)d_in[8];
    const float* b2       = (const float*)d_in[9];
    float* out = (float*)d_out;

    void *xhi,*xlo,*hhi,*hlo,*pw,*rw,*w1p,*w2p,*hid;
    cudaGetSymbolAddress(&xhi, g_x_hi);  cudaGetSymbolAddress(&xlo, g_x_lo);
    cudaGetSymbolAddress(&hhi, g_h_hi);  cudaGetSymbolAddress(&hlo, g_h_lo);
    cudaGetSymbolAddress(&pw, g_pw);     cudaGetSymbolAddress(&rw, g_rw);
    cudaGetSymbolAddress(&w1p, g_w1);    cudaGetSymbolAddress(&w2p, g_w2);
    cudaGetSymbolAddress(&hid, g_hid);

    constexpr int SM_PR = 4 * STG_OF(128, 256, 2, 32);          // 149504
    constexpr int SM_F1 = 4 * STG_OF(128, 256, 1, 64) + 1024;   // 209920
    constexpr int SM_F2 = 4 * STG_OF(128, 256, 1, 64);          // 208896
    cudaFuncSetAttribute((const void*)mma_gemm_kernel<0,512,512,128,256,2,32>,
                         cudaFuncAttributeMaxDynamicSharedMemorySize, SM_PR);
    cudaFuncSetAttribute((const void*)mma_gemm_kernel<1,512,512,128,256,2,32>,
                         cudaFuncAttributeMaxDynamicSharedMemorySize, SM_PR);
    cudaFuncSetAttribute((const void*)mma_gemm_kernel<2,512,2048,128,256,1,64>,
                         cudaFuncAttributeMaxDynamicSharedMemorySize, SM_F1);
    cudaFuncSetAttribute((const void*)mma_gemm_kernel<3,2048,512,128,256,1,64>,
                         cudaFuncAttributeMaxDynamicSharedMemorySize, SM_F2);

    conv8_kernel<<<(2*DIM*DIM/8+255)/256, 256>>>(proj_w,   (__half*)pw,  2*DIM*DIM);
    conv8_kernel<<<(2*DIM*DIM/8+255)/256, 256>>>(router_w, (__half*)rw,  2*DIM*DIM);
    conv8_kernel<<<(N_EXP*DIM*HID/8+255)/256, 256>>>(w1,   (__half*)w1p, N_EXP*DIM*HID);
    conv8_kernel<<<(N_EXP*HID*DIM/8+255)/256, 256>>>(w2,   (__half*)w2p, N_EXP*HID*DIM);

    split8_kernel<<<(N_TOK*DIM/8+255)/256, 256>>>(view[0],
        (__half*)xhi, (__half*)xlo, N_TOK*DIM);
    split8_kernel<<<(N_TOK*DIM/8+255)/256, 256>>>(view[1],
        (__half*)xhi + (size_t)N_TOK*DIM, (__half*)xlo + (size_t)N_TOK*DIM, N_TOK*DIM);

    dim3 gpr(DIM/256, N_TOKV/128);       // (2, 64)
    dim3 gf1(HID/256, MAX_TILES);        // (8, 272)
    dim3 gf2(DIM/256, MAX_TILES);        // (2, 272)

    mma_gemm_kernel<0,512,512,128,256,2,32><<<gpr, 256, SM_PR>>>(
        (const __half*)xhi, (const __half*)xlo, (const __half*)pw, proj_b);
    mma_gemm_kernel<1,512,512,128,256,2,32><<<gpr, 256, SM_PR>>>(
        (const __half*)hhi, (const __half*)hlo, (const __half*)rw, nullptr);
    reset_kernel<<<1, 32>>>();
    gate_kernel<<<N_TOKV/8, 256>>>(keys);
    scan_kernel<<<1, 1>>>();
    scatter_kernel<<<N_TOKV/128, 128>>>();
    mma_gemm_kernel<2,512,2048,128,256,1,64><<<gf1, 256, SM_F1>>>(
        (const __half*)hhi, nullptr, (const __half*)w1p, b1);
    mma_gemm_kernel<3,2048,512,128,256,1,64><<<gf2, 256, SM_F2>>>(
        (const __half*)hid, nullptr, (const __half*)w2p, b2);
    combine_kernel<<<(N_TOK*(DIM/4)+255)/256, 256>>>(out);
}

// round 14
// speedup vs baseline: 6.8642x; 1.0221x over previous
#include <cuda_runtime.h>
#include <cuda_fp16.h>
#include <math.h>
#include <stdint.h>

#define N_TOK    4096
#define N_TOKV   8192            // both views batched
#define DIM      512
#define N_EXP    16
#define TOPK     4
#define HID      2048
#define PAIR_CAP 36864           // 32768 pairs + 16 experts * 128 pad
#define MAX_TILES 272            // 32768/128 + 16

// ---------------- device scratch -------------------------------------------
__device__ __half g_x_hi [N_TOKV * DIM];
__device__ __half g_x_lo [N_TOKV * DIM];
__device__ __half g_h_hi [N_TOKV * DIM];
__device__ __half g_h_lo [N_TOKV * DIM];
__device__ float  g_r    [N_TOKV * DIM];
__device__ __half g_pw [2 * DIM * DIM];
__device__ __half g_rw [2 * DIM * DIM];
__device__ __half g_w1 [N_EXP * DIM * HID];
__device__ __half g_w2 [N_EXP * HID * DIM];
__device__ __half g_hid [(size_t)PAIR_CAP * HID];
__device__ __half g_slot[(size_t)PAIR_CAP * DIM];

__device__ int   g_pair_token[PAIR_CAP];      // zero-init: pads read row 0 (harmless)
__device__ float g_pair_gate [PAIR_CAP];
__device__ int   g_pairpos [N_TOKV * TOPK];
__device__ int   g_tok_eidx[N_TOKV * TOPK];
__device__ float g_tok_gate[N_TOKV * TOPK];
__device__ int   g_counts [N_EXP];
__device__ int   g_offsets[N_EXP + 1];
__device__ int   g_cursor [N_EXP];
__device__ int   g_tile_e [MAX_TILES];
__device__ int   g_tile_m0[MAX_TILES];
__device__ int   g_ntiles;

// ---------------- asm helpers ----------------------------------------------
__device__ __forceinline__ uint32_t smem_u32(const void* p) {
    uint32_t a;
    asm("{ .reg .u64 t; cvta.to.shared.u64 t, %1; cvt.u32.u64 %0, t; }" : "=r"(a) : "l"(p));
    return a;
}
__device__ __forceinline__ void cpa16(uint32_t s, const void* g) {
    asm volatile("cp.async.cg.shared.global [%0], [%1], 16;" :: "r"(s), "l"(g));
}
#define CP_COMMIT() asm volatile("cp.async.commit_group;" ::: "memory")
#define CP_WAIT(n)  asm volatile("cp.async.wait_group %0;" :: "n"(n) : "memory")

__device__ __forceinline__ void ldm_x4(uint32_t* r, uint32_t a) {
    asm volatile("ldmatrix.sync.aligned.m8n8.x4.shared.b16 {%0,%1,%2,%3}, [%4];"
        : "=r"(r[0]), "=r"(r[1]), "=r"(r[2]), "=r"(r[3]) : "r"(a));
}
__device__ __forceinline__ void ldm_x4_t(uint32_t* r, uint32_t a) {
    asm volatile("ldmatrix.sync.aligned.m8n8.x4.trans.shared.b16 {%0,%1,%2,%3}, [%4];"
        : "=r"(r[0]), "=r"(r[1]), "=r"(r[2]), "=r"(r[3]) : "r"(a));
}
__device__ __forceinline__ void mma_fp16(float* d, const uint32_t* a, uint32_t b0, uint32_t b1) {
    asm volatile("mma.sync.aligned.m16n8k16.row.col.f32.f16.f16.f32 "
        "{%0,%1,%2,%3}, {%4,%5,%6,%7}, {%8,%9}, {%0,%1,%2,%3};"
        : "+f"(d[0]), "+f"(d[1]), "+f"(d[2]), "+f"(d[3])
        : "r"(a[0]), "r"(a[1]), "r"(a[2]), "r"(a[3]), "r"(b0), "r"(b1));
}
__device__ __forceinline__ float gelu_exact(float x) {
    return 0.5f * x * (1.0f + erff(x * 0.70710678118654752440f));
}

// ---------------- HMMA GEMM ------------------------------------------------
// A row-major fp16 (ALIMB limbs), B row-major fp16 [K][N] (ldmatrix.trans).
// 8 warps, 64x64 warp tiles, 4-stage cp.async pipeline, ONE barrier/chunk,
// prefetch distance 2 (race-free: writes target 2-generation-old buffers).
// MODE 0: proj  (z = view from m0; +bias -> g_h hi/lo)
// MODE 1: router(z = view from m0; -> g_r fp32)
// MODE 2: ffn1  (indirect A rows; +bias,gelu -> g_hid fp16)
// MODE 3: ffn2  (+bias,*gate -> g_slot fp16)
template<int MODE, int KLEN, int NTOT, int BM, int BN, int ALIMB, int BK>
__global__ __launch_bounds__(256, 1) void mma_gemm_kernel(
    const __half* __restrict__ Ah, const __half* __restrict__ Al,
    const __half* __restrict__ B,
    const float* __restrict__ bias)
{
    constexpr int NC   = KLEN / BK;
    constexpr int KS   = BK / 16;
    constexpr int PA   = BK * 2 + 16;
    constexpr int PB   = BN * 2 + 16;
    constexpr int ABY  = BM * PA;
    constexpr int BOFF = ALIMB * ABY;
    constexpr int STG  = ALIMB * ABY + BK * PB;
    constexpr int WR   = BM / 64;
    constexpr int ARC  = BK / 8;
    constexpr int BRC  = BN / 8;
    constexpr int ACH  = BM * ARC;
    constexpr int BCH  = BK * BRC;

    int n0 = blockIdx.x * BN, m0, z;
    if (MODE <= 1) { m0 = blockIdx.y * BM; z = (m0 >= N_TOK) ? 1 : 0; }
    else {
        if ((int)blockIdx.y >= g_ntiles) return;
        z = g_tile_e[blockIdx.y]; m0 = g_tile_m0[blockIdx.y];
    }
    const __half* Bz = B + (size_t)z * KLEN * NTOT;

    extern __shared__ __align__(16) char smem[];
    uint32_t sb = smem_u32(smem);

    const int tid = threadIdx.x, lane = tid & 31, warp = tid >> 5;
    const int mw = (warp % WR) * 64, nw = (warp / WR) * 64;
    const int lr = lane & 15, lc = (lane >> 4) << 3;

    int* tok = (int*)(smem + 4 * STG);
    if (MODE == 2) {
        if (tid < BM) tok[tid] = g_pair_token[m0 + tid];
        __syncthreads();
    }

    auto load_stage = [&](int s, int c) {
        const int k0 = c * BK;
        const uint32_t base = sb + (uint32_t)s * STG;
#pragma unroll
        for (int ch = tid; ch < ACH; ch += 256) {
            int row = ch / ARC, kc = ch % ARC;
            const __half* src;
            if (MODE == 2) src = Ah + (size_t)tok[row] * KLEN + k0 + kc * 8;
            else           src = Ah + (size_t)(m0 + row) * KLEN + k0 + kc * 8;
            cpa16(base + row * PA + kc * 16, src);
            if (ALIMB == 2)
                cpa16(base + ABY + row * PA + kc * 16,
                      Al + (size_t)(m0 + row) * KLEN + k0 + kc * 8);
        }
#pragma unroll
        for (int ch = tid; ch < BCH; ch += 256) {
            int row = ch / BRC, nc = ch % BRC;
            cpa16(base + BOFF + row * PB + nc * 16,
                  Bz + (size_t)(k0 + row) * NTOT + n0 + nc * 8);
        }
    };

    float acc[4][8][4];
#pragma unroll
    for (int a = 0; a < 4; a++)
#pragma unroll
        for (int b = 0; b < 8; b++)
#pragma unroll
            for (int d = 0; d < 4; d++) acc[a][b][d] = 0.f;

    load_stage(0, 0); CP_COMMIT();
    if (NC > 1) { load_stage(1, 1); CP_COMMIT(); }

    for (int c = 0; c < NC; c++) {
        if (c + 2 < NC) { load_stage((c + 2) & 3, c + 2); CP_COMMIT(); CP_WAIT(2); }
        else if (c + 1 < NC) CP_WAIT(1);
        else CP_WAIT(0);
        __syncthreads();          // single barrier: 4 stages / distance-2 prefetch

        const uint32_t base = sb + (uint32_t)(c & 3) * STG;
#pragma unroll
        for (int ks = 0; ks < KS; ks++) {
            uint32_t a1[4][4], a2[4][4];
#pragma unroll
            for (int ms = 0; ms < 4; ms++) {
                uint32_t ad = base + (uint32_t)((mw + ms * 16 + lr) * PA + (ks * 16 + lc) * 2);
                ldm_x4(a1[ms], ad);
                if (ALIMB == 2) ldm_x4(a2[ms], ad + ABY);
            }
#pragma unroll
            for (int np = 0; np < 4; np++) {
                uint32_t bf[4];
                uint32_t bd = base + BOFF + (uint32_t)((ks * 16 + lr) * PB + (nw + np * 16 + lc) * 2);
                ldm_x4_t(bf, bd);
#pragma unroll
                for (int ms = 0; ms < 4; ms++)
#pragma unroll
                    for (int sub = 0; sub < 2; sub++) {
                        int ns = np * 2 + sub;
                        mma_fp16(acc[ms][ns], a1[ms], bf[sub*2], bf[sub*2+1]);
                        if (ALIMB == 2)
                            mma_fp16(acc[ms][ns], a2[ms], bf[sub*2], bf[sub*2+1]);
                    }
            }
        }
    }

    // ---- epilogue ----
    const int lrow = lane >> 2, lcol = (lane & 3) * 2;
#pragma unroll
    for (int ms = 0; ms < 4; ms++) {
        int r0 = m0 + mw + ms * 16 + lrow;
        float gt0 = 0.f, gt1 = 0.f;
        if (MODE == 3) { gt0 = g_pair_gate[r0]; gt1 = g_pair_gate[r0 + 8]; }
#pragma unroll
        for (int ns = 0; ns < 8; ns++) {
            int cc = n0 + nw + ns * 8 + lcol;
            float b0 = 0.f, b1 = 0.f;
            if (MODE != 1) {
                b0 = bias[(size_t)z * NTOT + cc];
                b1 = bias[(size_t)z * NTOT + cc + 1];
            }
            float v00 = acc[ms][ns][0] + b0, v01 = acc[ms][ns][1] + b1;
            float v10 = acc[ms][ns][2] + b0, v11 = acc[ms][ns][3] + b1;
            if (MODE == 2) {
                v00 = gelu_exact(v00); v01 = gelu_exact(v01);
                v10 = gelu_exact(v10); v11 = gelu_exact(v11);
            }
            if (MODE == 3) { v00 *= gt0; v01 *= gt0; v10 *= gt1; v11 *= gt1; }
            if (MODE == 1) {
                *(float2*)(g_r + (size_t)r0 * NTOT + cc)       = make_float2(v00, v01);
                *(float2*)(g_r + (size_t)(r0 + 8) * NTOT + cc) = make_float2(v10, v11);
            } else if (MODE == 2 || MODE == 3) {
                __half* OUT = (MODE == 2) ? g_hid : g_slot;
                *(__half2*)(OUT + (size_t)r0 * NTOT + cc) =
                    __halves2half2(__float2half(v00), __float2half(v01));
                *(__half2*)(OUT + (size_t)(r0 + 8) * NTOT + cc) =
                    __halves2half2(__float2half(v10), __float2half(v11));
            } else {
                __half h00 = __float2half(v00), h01 = __float2half(v01);
                __half h10 = __float2half(v10), h11 = __float2half(v11);
                *(__half2*)(g_h_hi + (size_t)r0 * NTOT + cc)       = __halves2half2(h00, h01);
                *(__half2*)(g_h_hi + (size_t)(r0 + 8) * NTOT + cc) = __halves2half2(h10, h11);
                *(__half2*)(g_h_lo + (size_t)r0 * NTOT + cc) =
                    __halves2half2(__float2half(v00 - __half2float(h00)),
                                   __float2half(v01 - __half2float(h01)));
                *(__half2*)(g_h_lo + (size_t)(r0 + 8) * NTOT + cc) =
                    __halves2half2(__float2half(v10 - __half2float(h10)),
                                   __float2half(v11 - __half2float(h11)));
            }
        }
    }
}

// ---------------- fused prep: weight converts + view splits + reset ---------
__device__ __forceinline__ void conv8_at(const float* __restrict__ in,
                                         __half* __restrict__ out, long i)
{
    float4 a = *(const float4*)(in + i);
    float4 b = *(const float4*)(in + i + 4);
    float v[8] = {a.x, a.y, a.z, a.w, b.x, b.y, b.z, b.w};
    union { __half2 p[4]; uint4 u; } ph;
#pragma unroll
    for (int j = 0; j < 4; j++)
        ph.p[j] = __halves2half2(__float2half(v[2*j]), __float2half(v[2*j+1]));
    *(uint4*)(out + i) = ph.u;
}
__device__ __forceinline__ void split8_at(const float* __restrict__ in,
                                          __half* __restrict__ hi,
                                          __half* __restrict__ lo, long i)
{
    float4 a = *(const float4*)(in + i);
    float4 b = *(const float4*)(in + i + 4);
    float v[8] = {a.x, a.y, a.z, a.w, b.x, b.y, b.z, b.w};
    union { __half2 p[4]; uint4 u; } ph, pl;
#pragma unroll
    for (int j = 0; j < 4; j++) {
        __half h0 = __float2half(v[2*j]);
        __half h1 = __float2half(v[2*j+1]);
        ph.p[j] = __halves2half2(h0, h1);
        pl.p[j] = __halves2half2(
            __float2half(v[2*j]   - __half2float(h0)),
            __float2half(v[2*j+1] - __half2float(h1)));
    }
    *(uint4*)(hi + i) = ph.u;
    *(uint4*)(lo + i) = pl.u;
}

#define C_W  ((long)N_EXP * DIM * HID / 8)     // 2097152 chunks each for w1,w2
#define C_P  ((long)2 * DIM * DIM / 8)         // 65536 chunks each for pw,rw
#define C_X  ((long)N_TOK * DIM / 8)           // 262144 chunks each view
#define PREP_CHUNKS (2*C_W + 2*C_P + 2*C_X)    // 4849664

__global__ __launch_bounds__(256) void prep_kernel(
    const float* __restrict__ w1, const float* __restrict__ w2,
    const float* __restrict__ pw, const float* __restrict__ rw,
    const float* __restrict__ v0, const float* __restrict__ v1)
{
    long id = (long)blockIdx.x * 256 + threadIdx.x;
    if (blockIdx.x == 0 && threadIdx.x < N_EXP) g_counts[threadIdx.x] = 0;
    if (id >= PREP_CHUNKS) return;
    if (id < C_W) { conv8_at(w1, g_w1, id * 8); return; }
    id -= C_W;
    if (id < C_W) { conv8_at(w2, g_w2, id * 8); return; }
    id -= C_W;
    if (id < C_P) { conv8_at(pw, g_pw, id * 8); return; }
    id -= C_P;
    if (id < C_P) { conv8_at(rw, g_rw, id * 8); return; }
    id -= C_P;
    if (id < C_X) { split8_at(v0, g_x_hi, g_x_lo, id * 8); return; }
    id -= C_X;
    split8_at(v1, g_x_hi + (size_t)N_TOK * DIM, g_x_lo + (size_t)N_TOK * DIM, id * 8);
}

// ---------------- routing kernels -------------------------------------------
// warp-per-token gate: 8 tokens/block, keys staged in smem
__global__ __launch_bounds__(256) void gate_kernel(const float* __restrict__ keys)
{
    __shared__ float ks[N_EXP][DIM];
    const int tid = threadIdx.x;
    for (int i = tid; i < N_EXP * DIM; i += 256)
        ks[i >> 9][i & 511] = keys[i];
    __syncthreads();

    const int warp = tid >> 5, lane = tid & 31;
    const int t = blockIdx.x * 8 + warp;
    const float* rr = g_r + (size_t)t * DIM;
    float rv[16];
#pragma unroll
    for (int j = 0; j < 16; j++) rv[j] = rr[lane + 32 * j];

    float lg[N_EXP];
#pragma unroll
    for (int e = 0; e < N_EXP; e++) {
        float s = 0.f;
#pragma unroll
        for (int j = 0; j < 16; j++) {
            float d = rv[j] - ks[e][lane + 32 * j];
            s = fmaf(d, d, s);
        }
#pragma unroll
        for (int o = 16; o > 0; o >>= 1)
            s += __shfl_xor_sync(0xFFFFFFFF, s, o);
        lg[e] = -sqrtf(fmaxf(s, 0.f));
    }
    if (lane == 0) {
        int idx[TOPK]; float val[TOPK]; bool used[N_EXP];
#pragma unroll
        for (int i = 0; i < N_EXP; i++) used[i] = false;
        for (int s2 = 0; s2 < TOPK; s2++) {
            int bi = -1; float bv = -1e30f;
            for (int i = 0; i < N_EXP; i++)
                if (!used[i] && lg[i] > bv) { bv = lg[i]; bi = i; }
            used[bi] = true; idx[s2] = bi; val[s2] = bv;
        }
        float mx = val[0], ex[TOPK], se = 0.f;
        for (int s2 = 0; s2 < TOPK; s2++) { ex[s2] = expf(val[s2] - mx); se += ex[s2]; }
        float inv = 1.0f / se;
        for (int s2 = 0; s2 < TOPK; s2++) {
            g_tok_eidx[t*TOPK + s2] = idx[s2];
            g_tok_gate[t*TOPK + s2] = ex[s2] * inv;
            atomicAdd(&g_counts[idx[s2]], 1);
        }
    }
}

__global__ void scan_kernel() {
    if (threadIdx.x == 0) {
        int o = 0, nt = 0;
        for (int e = 0; e < N_EXP; e++) {
            g_offsets[e] = o; g_cursor[e] = o;
            int seg = ((g_counts[e] + 127) >> 7) << 7;       // 128-aligned
            for (int i = 0; i < seg / 128; i++) { g_tile_e[nt] = e; g_tile_m0[nt] = o + (i << 7); nt++; }
            o += seg;
        }
        g_offsets[N_EXP] = o;
        g_ntiles = nt;
    }
}

__global__ __launch_bounds__(128) void scatter_kernel() {
    int t = blockIdx.x * 128 + threadIdx.x;
    if (t >= N_TOKV) return;
    for (int s = 0; s < TOPK; s++) {
        int e = g_tok_eidx[t*TOPK + s];
        int p = atomicAdd(&g_cursor[e], 1);
        g_pair_token[p] = t;
        g_pair_gate[p]  = g_tok_gate[t*TOPK + s];
        g_pairpos[t*TOPK + s] = p;
    }
}

// out[t] = sum over both views' 4 pairs each (8 slots, fp16 slot buffer)
__global__ __launch_bounds__(256) void combine_kernel(float* __restrict__ out)
{
    int idx = blockIdx.x * 256 + threadIdx.x;
    if (idx >= N_TOK * (DIM/4)) return;
    int t = idx >> 7, d = (idx & 127) << 2;
    float acc0 = 0.f, acc1 = 0.f, acc2 = 0.f, acc3 = 0.f;
#pragma unroll
    for (int s = 0; s < TOPK; s++) {
        int p0 = g_pairpos[t*TOPK + s];
        int p1 = g_pairpos[(t + N_TOK)*TOPK + s];
        uint2 u0 = *(const uint2*)(g_slot + (size_t)p0 * DIM + d);
        uint2 u1 = *(const uint2*)(g_slot + (size_t)p1 * DIM + d);
        float2 a0 = __half22float2(*(__half2*)&u0.x);
        float2 a1 = __half22float2(*(__half2*)&u0.y);
        float2 b0 = __half22float2(*(__half2*)&u1.x);
        float2 b1 = __half22float2(*(__half2*)&u1.y);
        acc0 += a0.x + b0.x; acc1 += a0.y + b0.y;
        acc2 += a1.x + b1.x; acc3 += a1.y + b1.y;
    }
    *(float4*)(out + (size_t)t * DIM + d) = make_float4(acc0, acc1, acc2, acc3);
}

// ---------------- host -----------------------------------------------------
#define STG_OF(BM, BN, AL, BK) ((AL) * (BM) * ((BK)*2+16) + (BK) * ((BN)*2+16))

extern "C" void kernel_launch(void* const* d_in, const int* in_sizes, int n_in,
                              void* d_out, int out_size)
{
    const float* view[2]  = {(const float*)d_in[0], (const float*)d_in[1]};
    const float* proj_w   = (const float*)d_in[2];
    const float* proj_b   = (const float*)d_in[3];
    const float* router_w = (const float*)d_in[4];
    const float* keys     = (const float*)d_in[5];
    const float* w1       = (const float*)d_in[6];
    const float* b1       = (const float*)d_in[7];
    const float* w2       = (const float*)d_in[8];
    const float* b2       = (const float*)d_in[9];
    float* out = (float*)d_out;

    void *xhi,*xlo,*hhi,*hlo,*pw,*rw,*w1p,*w2p,*hid;
    cudaGetSymbolAddress(&xhi, g_x_hi);  cudaGetSymbolAddress(&xlo, g_x_lo);
    cudaGetSymbolAddress(&hhi, g_h_hi);  cudaGetSymbolAddress(&hlo, g_h_lo);
    cudaGetSymbolAddress(&pw, g_pw);     cudaGetSymbolAddress(&rw, g_rw);
    cudaGetSymbolAddress(&w1p, g_w1);    cudaGetSymbolAddress(&w2p, g_w2);
    cudaGetSymbolAddress(&hid, g_hid);

    constexpr int SM_PR = 4 * STG_OF(128, 256, 2, 32);          // 149504
    constexpr int SM_F1 = 4 * STG_OF(128, 256, 1, 64) + 1024;   // 209920
    constexpr int SM_F2 = 4 * STG_OF(128, 256, 1, 64);          // 208896
    cudaFuncSetAttribute((const void*)mma_gemm_kernel<0,512,512,128,256,2,32>,
                         cudaFuncAttributeMaxDynamicSharedMemorySize, SM_PR);
    cudaFuncSetAttribute((const void*)mma_gemm_kernel<1,512,512,128,256,2,32>,
                         cudaFuncAttributeMaxDynamicSharedMemorySize, SM_PR);
    cudaFuncSetAttribute((const void*)mma_gemm_kernel<2,512,2048,128,256,1,64>,
                         cudaFuncAttributeMaxDynamicSharedMemorySize, SM_F1);
    cudaFuncSetAttribute((const void*)mma_gemm_kernel<3,2048,512,128,256,1,64>,
                         cudaFuncAttributeMaxDynamicSharedMemorySize, SM_F2);

    // one fused prep launch: all weight converts + both view splits + reset
    prep_kernel<<<(int)((PREP_CHUNKS + 255) / 256), 256>>>(
        w1, w2, proj_w, router_w, view[0], view[1]);

    dim3 gpr(DIM/256, N_TOKV/128);       // (2, 64)
    dim3 gf1(HID/256, MAX_TILES);        // (8, 272)
    dim3 gf2(DIM/256, MAX_TILES);        // (2, 272)

    mma_gemm_kernel<0,512,512,128,256,2,32><<<gpr, 256, SM_PR>>>(
        (const __half*)xhi, (const __half*)xlo, (const __half*)pw, proj_b);
    mma_gemm_kernel<1,512,512,128,256,2,32><<<gpr, 256, SM_PR>>>(
        (const __half*)hhi, (const __half*)hlo, (const __half*)rw, nullptr);
    gate_kernel<<<N_TOKV/8, 256>>>(keys);
    scan_kernel<<<1, 1>>>();
    scatter_kernel<<<N_TOKV/128, 128>>>();
    mma_gemm_kernel<2,512,2048,128,256,1,64><<<gf1, 256, SM_F1>>>(
        (const __half*)hhi, nullptr, (const __half*)w1p, b1);
    mma_gemm_kernel<3,2048,512,128,256,1,64><<<gf2, 256, SM_F2>>>(
        (const __half*)hid, nullptr, (const __half*)w2p, b2);
    combine_kernel<<<(N_TOK*(DIM/4)+255)/256, 256>>>(out);
}